// round 2
// baseline (speedup 1.0000x reference)
#include <cuda_runtime.h>
#include <math.h>

// Shapes (fixed by the problem)
#define NB   2
#define TT   16
#define SS   256
#define DD   1024
#define MTOK (NB*TT*SS)        // 8192 tokens
#define QKVC (3*DD)            // 3072
#define HEADS 8
#define DH    64
#define SCALE 0.125f           // (1024/16)^-0.5

// Scratch (static device allocation — allowed; no cudaMalloc anywhere)
__device__ float g_qkv[MTOK * QKVC];   // [8192, 3072]
__device__ float g_att[MTOK * DD];     // [8192, 1024] concat(spatial, temporal)

// ---------------------------------------------------------------------------
// Tiled SGEMM: C[M,N] = A[M,K] @ B[K,N] (+ bias). M,N,K divisible by tiles.
// BM=BN=128, BK=16, 256 threads, 8x8 per-thread microtile.
// ---------------------------------------------------------------------------
#define BM 128
#define BN 128
#define BK 16

__global__ __launch_bounds__(256) void sgemm_kernel(
    const float* __restrict__ A, const float* __restrict__ B,
    float* __restrict__ C, int M, int N, int K,
    const float* __restrict__ bias)
{
    __shared__ float As[BK][BM];
    __shared__ float Bs[BK][BN];

    const int tid = threadIdx.x;
    const int bx = blockIdx.x;   // N tile
    const int by = blockIdx.y;   // M tile
    const int tx = tid & 15;     // 0..15
    const int ty = tid >> 4;     // 0..15

    const int aRow  = tid >> 2;   // 0..63
    const int aCol4 = tid & 3;    // 0..3  (float4 within 16-wide k)
    const int bRow  = tid >> 5;   // 0..7
    const int bCol4 = tid & 31;   // 0..31

    const float* Aptr = A + (long)(by * BM) * K;
    const float* Bptr = B + bx * BN;

    float acc[8][8];
    #pragma unroll
    for (int i = 0; i < 8; i++)
        #pragma unroll
        for (int j = 0; j < 8; j++) acc[i][j] = 0.f;

    for (int k0 = 0; k0 < K; k0 += BK) {
        // A tile: 128 rows x 16 cols, store transposed As[k][m]
        #pragma unroll
        for (int i = 0; i < 2; i++) {
            int r = aRow + i * 64;
            float4 v = *(const float4*)(Aptr + (long)r * K + k0 + aCol4 * 4);
            As[aCol4 * 4 + 0][r] = v.x;
            As[aCol4 * 4 + 1][r] = v.y;
            As[aCol4 * 4 + 2][r] = v.z;
            As[aCol4 * 4 + 3][r] = v.w;
        }
        // B tile: 16 rows x 128 cols
        #pragma unroll
        for (int i = 0; i < 2; i++) {
            int r = bRow + i * 8;
            float4 v = *(const float4*)(Bptr + (long)(k0 + r) * N + bCol4 * 4);
            *(float4*)&Bs[r][bCol4 * 4] = v;
        }
        __syncthreads();

        #pragma unroll
        for (int kk = 0; kk < BK; kk++) {
            float a[8], b[8];
            #pragma unroll
            for (int i = 0; i < 8; i++) a[i] = As[kk][ty * 8 + i];
            #pragma unroll
            for (int j = 0; j < 8; j++) b[j] = Bs[kk][tx * 8 + j];
            #pragma unroll
            for (int i = 0; i < 8; i++)
                #pragma unroll
                for (int j = 0; j < 8; j++)
                    acc[i][j] += a[i] * b[j];
        }
        __syncthreads();
    }

    #pragma unroll
    for (int i = 0; i < 8; i++) {
        int row = by * BM + ty * 8 + i;
        #pragma unroll
        for (int j4 = 0; j4 < 2; j4++) {
            int col = bx * BN + tx * 8 + j4 * 4;
            float4 v;
            v.x = acc[i][j4 * 4 + 0];
            v.y = acc[i][j4 * 4 + 1];
            v.z = acc[i][j4 * 4 + 2];
            v.w = acc[i][j4 * 4 + 3];
            if (bias) {
                v.x += bias[col + 0];
                v.y += bias[col + 1];
                v.z += bias[col + 2];
                v.w += bias[col + 3];
            }
            *(float4*)(C + (long)row * N + col) = v;
        }
    }
}

// ---------------------------------------------------------------------------
// Spatial attention: one block per (n, t, h). 256 threads = 256 queries.
// K,V tiles (256 x 64 fp32 each) live in 128 KB dynamic smem.
// Per-thread flash-style online softmax; q and acc in registers.
// qkv layout per token (3072 cols): [q_s | q_t | k_s | k_t | v_s | v_t] x 512
// ---------------------------------------------------------------------------
__global__ __launch_bounds__(256, 1) void spatial_attn_kernel(
    const float* __restrict__ qkv, float* __restrict__ att)
{
    extern __shared__ float smem[];
    float* Ks = smem;            // 256*64
    float* Vs = smem + 256 * 64; // 256*64

    const int b = blockIdx.x;
    const int h = b & 7;
    const int t = (b >> 3) & 15;
    const int n = b >> 7;
    const int tid = threadIdx.x;
    const int frame_base = (n * TT + t) * SS;

    const float4* qkv4 = (const float4*)qkv;

    // Load K (cols 1024+h*64) and V (cols 2048+h*64) for all 256 keys.
    for (int idx = tid; idx < 256 * 16; idx += 256) {
        int s  = idx >> 4;
        int d4 = idx & 15;
        int base4 = (frame_base + s) * (QKVC / 4);          // 768
        ((float4*)Ks)[idx] = qkv4[base4 + 256 + h * 16 + d4]; // 1024/4
        ((float4*)Vs)[idx] = qkv4[base4 + 512 + h * 16 + d4]; // 2048/4
    }
    __syncthreads();

    const int s = tid;
    const int tok = frame_base + s;

    float4 q[16];
    #pragma unroll
    for (int i = 0; i < 16; i++)
        q[i] = qkv4[tok * (QKVC / 4) + h * 16 + i];          // q_s at col 0

    float m = -1e30f, ssum = 0.f;
    float4 acc[16];
    #pragma unroll
    for (int i = 0; i < 16; i++) acc[i] = make_float4(0.f, 0.f, 0.f, 0.f);

    for (int k = 0; k < 256; k++) {
        const float4* kp = (const float4*)(Ks + k * 64);
        float dot = 0.f;
        #pragma unroll
        for (int i = 0; i < 16; i++) {
            float4 kv = kp[i];
            dot += q[i].x * kv.x + q[i].y * kv.y + q[i].z * kv.z + q[i].w * kv.w;
        }
        dot *= SCALE;
        if (dot > m) {
            float corr = __expf(m - dot);   // 0 on first iteration (m=-1e30)
            ssum *= corr;
            #pragma unroll
            for (int i = 0; i < 16; i++) {
                acc[i].x *= corr; acc[i].y *= corr;
                acc[i].z *= corr; acc[i].w *= corr;
            }
            m = dot;
        }
        float p = __expf(dot - m);
        ssum += p;
        const float4* vp = (const float4*)(Vs + k * 64);
        #pragma unroll
        for (int i = 0; i < 16; i++) {
            float4 vv = vp[i];
            acc[i].x += p * vv.x; acc[i].y += p * vv.y;
            acc[i].z += p * vv.z; acc[i].w += p * vv.w;
        }
    }

    float inv = 1.f / ssum;
    float4* out4 = (float4*)att;
    #pragma unroll
    for (int i = 0; i < 16; i++) {
        float4 v = acc[i];
        v.x *= inv; v.y *= inv; v.z *= inv; v.w *= inv;
        out4[tok * (DD / 4) + h * 16 + i] = v;   // spatial half: cols [0,512)
    }
}

// ---------------------------------------------------------------------------
// Temporal attention: one block per (n, s). 128 threads = (head, query_t).
// K_t,V_t tiles (16 x 512 fp32, padded stride) in dynamic smem.
// ---------------------------------------------------------------------------
#define TKS 516   // padded row stride (floats) to reduce bank conflicts

__global__ __launch_bounds__(128, 1) void temporal_attn_kernel(
    const float* __restrict__ qkv, float* __restrict__ att)
{
    extern __shared__ float smem[];
    float* Ks = smem;               // 16 * TKS
    float* Vs = smem + 16 * TKS;

    const int b = blockIdx.x;
    const int s = b & 255;
    const int n = b >> 8;
    const int tid = threadIdx.x;

    // Load K_t (cols 1536..2047) and V_t (cols 2560..3071) for all 16 frames.
    for (int idx = tid; idx < 16 * 128; idx += 128) {   // 128 float4 per row
        int t  = idx >> 7;
        int c4 = idx & 127;
        int tok = (n * TT + t) * SS + s;
        const float4* base = (const float4*)(qkv + tok * QKVC);
        ((float4*)(Ks + t * TKS))[c4] = base[384 + c4];  // 1536/4
        ((float4*)(Vs + t * TKS))[c4] = base[640 + c4];  // 2560/4
    }
    __syncthreads();

    const int h  = tid >> 4;   // 0..7
    const int tq = tid & 15;   // 0..15
    const int tokq = (n * TT + tq) * SS + s;

    float4 q[16];
    const float4* qb = (const float4*)(qkv + tokq * QKVC);
    #pragma unroll
    for (int i = 0; i < 16; i++) q[i] = qb[128 + h * 16 + i];   // q_t at col 512

    float l[16];
    float m = -1e30f;
    #pragma unroll
    for (int kt = 0; kt < 16; kt++) {
        const float4* kp = (const float4*)(Ks + kt * TKS + h * 64);
        float dot = 0.f;
        #pragma unroll
        for (int i = 0; i < 16; i++) {
            float4 kv = kp[i];
            dot += q[i].x * kv.x + q[i].y * kv.y + q[i].z * kv.z + q[i].w * kv.w;
        }
        l[kt] = dot * SCALE;
        m = fmaxf(m, l[kt]);
    }
    float ssum = 0.f;
    #pragma unroll
    for (int kt = 0; kt < 16; kt++) { l[kt] = __expf(l[kt] - m); ssum += l[kt]; }
    float inv = 1.f / ssum;

    float4 acc[16];
    #pragma unroll
    for (int i = 0; i < 16; i++) acc[i] = make_float4(0.f, 0.f, 0.f, 0.f);
    #pragma unroll
    for (int kt = 0; kt < 16; kt++) {
        float p = l[kt] * inv;
        const float4* vp = (const float4*)(Vs + kt * TKS + h * 64);
        #pragma unroll
        for (int i = 0; i < 16; i++) {
            float4 vv = vp[i];
            acc[i].x += p * vv.x; acc[i].y += p * vv.y;
            acc[i].z += p * vv.z; acc[i].w += p * vv.w;
        }
    }

    float4* out4 = (float4*)att;
    #pragma unroll
    for (int i = 0; i < 16; i++)
        out4[tokq * (DD / 4) + 128 + h * 16 + i] = acc[i];  // temporal half: cols [512,1024)
}

// ---------------------------------------------------------------------------
// Launch
// ---------------------------------------------------------------------------
extern "C" void kernel_launch(void* const* d_in, const int* in_sizes, int n_in,
                              void* d_out, int out_size)
{
    const float* x     = (const float*)d_in[0];   // [2,16,256,1024]
    const float* Wqkv  = (const float*)d_in[1];   // [1024, 3072]
    const float* Wproj = (const float*)d_in[2];   // [1024, 1024]
    const float* bproj = (const float*)d_in[3];   // [1024]
    float* out = (float*)d_out;                   // [2,16,256,1024]

    float* qkv = nullptr;
    float* att = nullptr;
    cudaGetSymbolAddress((void**)&qkv, g_qkv);
    cudaGetSymbolAddress((void**)&att, g_att);

    const int spat_smem = 2 * 256 * 64 * (int)sizeof(float);   // 131072
    const int temp_smem = 2 * 16 * TKS * (int)sizeof(float);   // 66048
    cudaFuncSetAttribute(spatial_attn_kernel,
                         cudaFuncAttributeMaxDynamicSharedMemorySize, spat_smem);
    cudaFuncSetAttribute(temporal_attn_kernel,
                         cudaFuncAttributeMaxDynamicSharedMemorySize, temp_smem);

    // 1) qkv = x @ Wqkv   (M=8192, N=3072, K=1024)
    sgemm_kernel<<<dim3(QKVC / BN, MTOK / BM), 256>>>(
        x, Wqkv, qkv, MTOK, QKVC, DD, nullptr);

    // 2) spatial + temporal attention -> g_att (concat halves)
    spatial_attn_kernel<<<NB * TT * HEADS, 256, spat_smem>>>(qkv, att);
    temporal_attn_kernel<<<NB * SS, 128, temp_smem>>>(qkv, att);

    // 3) out = g_att @ Wproj + bproj   (M=8192, N=1024, K=1024)
    sgemm_kernel<<<dim3(DD / BN, MTOK / BM), 256>>>(
        att, Wproj, out, MTOK, DD, DD, bproj);
}

// round 6
// speedup vs baseline: 2.2610x; 2.2610x over previous
#include <cuda_runtime.h>
#include <cuda_bf16.h>
#include <cstdint>
#include <math.h>

// Shapes (fixed by the problem)
#define NB   2
#define TT   16
#define SS   256
#define DD   1024
#define MTOK (NB*TT*SS)        // 8192 tokens
#define QKVC (3*DD)            // 3072
#define HEADS 8
#define DH    64
#define SCALE 0.125f           // (1024/16)^-0.5

// ---------------------------------------------------------------------------
// Scratch (static device allocations — no cudaMalloc anywhere)
// ---------------------------------------------------------------------------
__device__ float g_qkv[MTOK * QKVC];                        // [8192, 3072] fp32
__device__ __align__(16) __nv_bfloat16 g_xhi[MTOK * DD];
__device__ __align__(16) __nv_bfloat16 g_xlo[MTOK * DD];
__device__ __align__(16) __nv_bfloat16 g_ahi[MTOK * DD];    // attention out hi
__device__ __align__(16) __nv_bfloat16 g_alo[MTOK * DD];    // attention out lo
__device__ __align__(16) __nv_bfloat16 g_wqh[QKVC * DD];    // Wqkv^T [3072,1024]
__device__ __align__(16) __nv_bfloat16 g_wql[QKVC * DD];
__device__ __align__(16) __nv_bfloat16 g_wph[DD * DD];      // Wproj^T [1024,1024]
__device__ __align__(16) __nv_bfloat16 g_wpl[DD * DD];

// ---------------------------------------------------------------------------
// PTX helpers: mma.sync + ldmatrix + cp.async (sm_80+, safe on sm_103 target)
// ---------------------------------------------------------------------------
__device__ __forceinline__ uint32_t smem_to_u32(const void* p) {
    uint32_t a;
    asm("{ .reg .u64 t; cvta.to.shared.u64 t, %1; cvt.u32.u64 %0, t; }" : "=r"(a) : "l"(p));
    return a;
}

__device__ __forceinline__ void ldmatrix_x4(uint32_t& r0, uint32_t& r1,
                                            uint32_t& r2, uint32_t& r3, uint32_t addr) {
    asm volatile("ldmatrix.sync.aligned.m8n8.x4.shared.b16 {%0,%1,%2,%3}, [%4];"
                 : "=r"(r0), "=r"(r1), "=r"(r2), "=r"(r3) : "r"(addr));
}

__device__ __forceinline__ void mma16816(float* d, uint32_t a0, uint32_t a1,
                                         uint32_t a2, uint32_t a3,
                                         uint32_t b0, uint32_t b1) {
    asm volatile(
        "mma.sync.aligned.m16n8k16.row.col.f32.bf16.bf16.f32 "
        "{%0,%1,%2,%3}, {%4,%5,%6,%7}, {%8,%9}, {%0,%1,%2,%3};"
        : "+f"(d[0]), "+f"(d[1]), "+f"(d[2]), "+f"(d[3])
        : "r"(a0), "r"(a1), "r"(a2), "r"(a3), "r"(b0), "r"(b1));
}

__device__ __forceinline__ void cp_async16(uint32_t saddr, const void* gaddr) {
    asm volatile("cp.async.cg.shared.global [%0], [%1], 16;" :: "r"(saddr), "l"(gaddr));
}
__device__ __forceinline__ void cp_async_commit_wait() {
    asm volatile("cp.async.commit_group;");
    asm volatile("cp.async.wait_group 0;");
}

// ---------------------------------------------------------------------------
// bf16x3 tensor-core GEMM via mma.sync: C[M,N] = A[M,K] @ B[N,K]^T (+ bias)
// CTA tile 128x128, 8 warps (warp tile 32x64), K-chunk 32.
// SMEM rows padded to 80B -> ldmatrix phases conflict-free.
// ---------------------------------------------------------------------------
#define RS 40            // padded row stride in bf16 elems (80 bytes)
#define TILE_F (128*RS)  // floats.. bf16 elems per tile region

__global__ __launch_bounds__(256, 2) void gemm_bf16x3_mma(
    const __nv_bfloat16* __restrict__ Ahi, const __nv_bfloat16* __restrict__ Alo,
    const __nv_bfloat16* __restrict__ Bhi, const __nv_bfloat16* __restrict__ Blo,
    float* __restrict__ C, int M, int N, int K,
    const float* __restrict__ bias)
{
    __shared__ __nv_bfloat16 sm[4 * TILE_F];   // Ahi | Alo | Bhi | Blo
    __nv_bfloat16* sAhi = sm;
    __nv_bfloat16* sAlo = sm + TILE_F;
    __nv_bfloat16* sBhi = sm + 2 * TILE_F;
    __nv_bfloat16* sBlo = sm + 3 * TILE_F;

    const int tid  = threadIdx.x;
    const int wid  = tid >> 5;
    const int lane = tid & 31;
    const int warp_m = wid & 3;     // 0..3  -> 32 rows each
    const int warp_n = wid >> 2;    // 0..1  -> 64 cols each
    const int m0 = blockIdx.y * 128;
    const int n0 = blockIdx.x * 128;

    const uint32_t sbase = smem_to_u32(sm);
    const uint32_t uAhi = sbase;
    const uint32_t uAlo = sbase + TILE_F * 2;
    const uint32_t uBhi = sbase + 2 * TILE_F * 2;
    const uint32_t uBlo = sbase + 3 * TILE_F * 2;

    float acc[2][8][4];
    #pragma unroll
    for (int i = 0; i < 2; i++)
        #pragma unroll
        for (int j = 0; j < 8; j++)
            #pragma unroll
            for (int q = 0; q < 4; q++) acc[i][j][q] = 0.f;

    // per-thread load slots: 2 uint4 per tile per chunk
    const int lr0 = tid >> 2;            // rows 0..63
    const int lc0 = tid & 3;             // col4 0..3
    // (second slot = rows 64..127)

    for (int k0 = 0; k0 < K; k0 += 32) {
        // ---- global -> smem (cp.async), 4 tiles of 128x32 bf16 ----
        #pragma unroll
        for (int half = 0; half < 2; half++) {
            const int r = lr0 + half * 64;
            const uint32_t soff = (uint32_t)(r * RS + lc0 * 8) * 2;
            const size_t  aoff = (size_t)(m0 + r) * K + k0 + lc0 * 8;
            const size_t  boff = (size_t)(n0 + r) * K + k0 + lc0 * 8;
            cp_async16(uAhi + soff, Ahi + aoff);
            cp_async16(uAlo + soff, Alo + aoff);
            cp_async16(uBhi + soff, Bhi + boff);
            cp_async16(uBlo + soff, Blo + boff);
        }
        cp_async_commit_wait();
        __syncthreads();

        // ---- compute: 2 k16 steps ----
        #pragma unroll
        for (int ks = 0; ks < 2; ks++) {
            // A fragments (hi & lo), msub = 0,1
            uint32_t ah[2][4], al[2][4];
            const int am = (lane & 15);
            const int ak = (ks * 16 + ((lane >> 4) << 3)) * 2;  // byte offset in row
            #pragma unroll
            for (int ms = 0; ms < 2; ms++) {
                const uint32_t arow = (uint32_t)(warp_m * 32 + ms * 16 + am) * (RS * 2) + ak;
                ldmatrix_x4(ah[ms][0], ah[ms][1], ah[ms][2], ah[ms][3], uAhi + arow);
                ldmatrix_x4(al[ms][0], al[ms][1], al[ms][2], al[ms][3], uAlo + arow);
            }

            // B hi fragments: 4 x ldmatrix.x4 -> 8 n8-frags
            const int bn = (lane & 7) + ((lane >> 4) << 3);          // row within n16 pair
            const int bk = (ks * 16 + (((lane >> 3) & 1) << 3)) * 2; // byte offset
            uint32_t bh[4][4];
            #pragma unroll
            for (int nn = 0; nn < 4; nn++) {
                const uint32_t brow = (uint32_t)(warp_n * 64 + nn * 16 + bn) * (RS * 2) + bk;
                ldmatrix_x4(bh[nn][0], bh[nn][1], bh[nn][2], bh[nn][3], uBhi + brow);
            }
            // Ahi*Bhi + Alo*Bhi
            #pragma unroll
            for (int ms = 0; ms < 2; ms++)
                #pragma unroll
                for (int nn = 0; nn < 4; nn++) {
                    mma16816(acc[ms][nn * 2 + 0], ah[ms][0], ah[ms][1], ah[ms][2], ah[ms][3],
                             bh[nn][0], bh[nn][1]);
                    mma16816(acc[ms][nn * 2 + 1], ah[ms][0], ah[ms][1], ah[ms][2], ah[ms][3],
                             bh[nn][2], bh[nn][3]);
                    mma16816(acc[ms][nn * 2 + 0], al[ms][0], al[ms][1], al[ms][2], al[ms][3],
                             bh[nn][0], bh[nn][1]);
                    mma16816(acc[ms][nn * 2 + 1], al[ms][0], al[ms][1], al[ms][2], al[ms][3],
                             bh[nn][2], bh[nn][3]);
                }
            // B lo fragments (reuse bh regs) ; Ahi*Blo
            #pragma unroll
            for (int nn = 0; nn < 4; nn++) {
                const uint32_t brow = (uint32_t)(warp_n * 64 + nn * 16 + bn) * (RS * 2) + bk;
                ldmatrix_x4(bh[nn][0], bh[nn][1], bh[nn][2], bh[nn][3], uBlo + brow);
            }
            #pragma unroll
            for (int ms = 0; ms < 2; ms++)
                #pragma unroll
                for (int nn = 0; nn < 4; nn++) {
                    mma16816(acc[ms][nn * 2 + 0], ah[ms][0], ah[ms][1], ah[ms][2], ah[ms][3],
                             bh[nn][0], bh[nn][1]);
                    mma16816(acc[ms][nn * 2 + 1], ah[ms][0], ah[ms][1], ah[ms][2], ah[ms][3],
                             bh[nn][2], bh[nn][3]);
                }
        }
        __syncthreads();
    }

    // ---- epilogue: fragment layout c0,c1 -> (row=t/4, col=(t%4)*2), c2,c3 -> row+8
    const int orow = m0 + warp_m * 32 + (lane >> 2);
    const int ocol0 = n0 + warp_n * 64 + (lane & 3) * 2;
    #pragma unroll
    for (int ms = 0; ms < 2; ms++) {
        #pragma unroll
        for (int nf = 0; nf < 8; nf++) {
            const int col = ocol0 + nf * 8;
            float b0 = 0.f, b1 = 0.f;
            if (bias) { b0 = bias[col]; b1 = bias[col + 1]; }
            float2 v0 = make_float2(acc[ms][nf][0] + b0, acc[ms][nf][1] + b1);
            float2 v1 = make_float2(acc[ms][nf][2] + b0, acc[ms][nf][3] + b1);
            *(float2*)(C + (size_t)(orow + ms * 16) * N + col) = v0;
            *(float2*)(C + (size_t)(orow + ms * 16 + 8) * N + col) = v1;
        }
    }
}

// ---------------------------------------------------------------------------
// fp32 -> bf16 hi/lo split helpers
// ---------------------------------------------------------------------------
__device__ __forceinline__ void split1(float v, __nv_bfloat16& h, __nv_bfloat16& l) {
    h = __float2bfloat16_rn(v);
    l = __float2bfloat16_rn(v - __bfloat162float(h));
}

__global__ __launch_bounds__(256) void split_kernel(
    const float4* __restrict__ in, uint2* __restrict__ hi, uint2* __restrict__ lo, int n4)
{
    int i = blockIdx.x * blockDim.x + threadIdx.x;
    if (i >= n4) return;
    float4 v = in[i];
    union { __nv_bfloat16 b[4]; uint2 u; } H, L;
    split1(v.x, H.b[0], L.b[0]);
    split1(v.y, H.b[1], L.b[1]);
    split1(v.z, H.b[2], L.b[2]);
    split1(v.w, H.b[3], L.b[3]);
    hi[i] = H.u;
    lo[i] = L.u;
}

// W [K,N] fp32 -> T [N,K] bf16 hi/lo (transpose + split)
__global__ __launch_bounds__(256) void transpose_split(
    const float* __restrict__ W,
    __nv_bfloat16* __restrict__ Thi, __nv_bfloat16* __restrict__ Tlo,
    int K, int N)
{
    __shared__ float tile[32][33];
    const int n0 = blockIdx.x * 32;
    const int k0 = blockIdx.y * 32;
    for (int i = threadIdx.y; i < 32; i += 8)
        tile[i][threadIdx.x] = W[(size_t)(k0 + i) * N + n0 + threadIdx.x];
    __syncthreads();
    for (int i = threadIdx.y; i < 32; i += 8) {
        float v = tile[threadIdx.x][i];
        __nv_bfloat16 h, l;
        split1(v, h, l);
        size_t o = (size_t)(n0 + i) * K + k0 + threadIdx.x;
        Thi[o] = h;
        Tlo[o] = l;
    }
}

// ---------------------------------------------------------------------------
// Spatial attention: writes bf16 hi/lo directly (cols [0,512) of att)
// ---------------------------------------------------------------------------
__global__ __launch_bounds__(256, 1) void spatial_attn_kernel(
    const float* __restrict__ qkv,
    __nv_bfloat16* __restrict__ ahi, __nv_bfloat16* __restrict__ alo)
{
    extern __shared__ float fsm[];
    float* Ks = fsm;
    float* Vs = fsm + 256 * 64;

    const int b = blockIdx.x;
    const int h = b & 7;
    const int t = (b >> 3) & 15;
    const int n = b >> 7;
    const int tid = threadIdx.x;
    const int frame_base = (n * TT + t) * SS;

    const float4* qkv4 = (const float4*)qkv;
    for (int idx = tid; idx < 256 * 16; idx += 256) {
        int s  = idx >> 4;
        int d4 = idx & 15;
        int base4 = (frame_base + s) * (QKVC / 4);
        ((float4*)Ks)[idx] = qkv4[base4 + 256 + h * 16 + d4];
        ((float4*)Vs)[idx] = qkv4[base4 + 512 + h * 16 + d4];
    }
    __syncthreads();

    const int s = tid;
    const int tok = frame_base + s;
    float4 q[16];
    #pragma unroll
    for (int i = 0; i < 16; i++) q[i] = qkv4[tok * (QKVC / 4) + h * 16 + i];

    float m = -1e30f, ssum = 0.f;
    float4 acc[16];
    #pragma unroll
    for (int i = 0; i < 16; i++) acc[i] = make_float4(0.f, 0.f, 0.f, 0.f);

    for (int k = 0; k < 256; k++) {
        const float4* kp = (const float4*)(Ks + k * 64);
        float dot = 0.f;
        #pragma unroll
        for (int i = 0; i < 16; i++) {
            float4 kv = kp[i];
            dot += q[i].x * kv.x + q[i].y * kv.y + q[i].z * kv.z + q[i].w * kv.w;
        }
        dot *= SCALE;
        if (dot > m) {
            float corr = __expf(m - dot);
            ssum *= corr;
            #pragma unroll
            for (int i = 0; i < 16; i++) {
                acc[i].x *= corr; acc[i].y *= corr;
                acc[i].z *= corr; acc[i].w *= corr;
            }
            m = dot;
        }
        float p = __expf(dot - m);
        ssum += p;
        const float4* vp = (const float4*)(Vs + k * 64);
        #pragma unroll
        for (int i = 0; i < 16; i++) {
            float4 vv = vp[i];
            acc[i].x += p * vv.x; acc[i].y += p * vv.y;
            acc[i].z += p * vv.z; acc[i].w += p * vv.w;
        }
    }

    float inv = 1.f / ssum;
    uint2* hi4 = (uint2*)ahi;
    uint2* lo4 = (uint2*)alo;
    #pragma unroll
    for (int i = 0; i < 16; i++) {
        float vv[4] = { acc[i].x * inv, acc[i].y * inv, acc[i].z * inv, acc[i].w * inv };
        union { __nv_bfloat16 b[4]; uint2 u; } H, L;
        #pragma unroll
        for (int q4 = 0; q4 < 4; q4++) split1(vv[q4], H.b[q4], L.b[q4]);
        const int o = tok * (DD / 4) + h * 16 + i;   // cols [0,512)
        hi4[o] = H.u;
        lo4[o] = L.u;
    }
}

// ---------------------------------------------------------------------------
// Temporal attention: writes bf16 hi/lo directly (cols [512,1024) of att)
// ---------------------------------------------------------------------------
#define TKS 516

__global__ __launch_bounds__(128, 1) void temporal_attn_kernel(
    const float* __restrict__ qkv,
    __nv_bfloat16* __restrict__ ahi, __nv_bfloat16* __restrict__ alo)
{
    extern __shared__ float fsm[];
    float* Ks = fsm;
    float* Vs = fsm + 16 * TKS;

    const int b = blockIdx.x;
    const int s = b & 255;
    const int n = b >> 8;
    const int tid = threadIdx.x;

    for (int idx = tid; idx < 16 * 128; idx += 128) {
        int t  = idx >> 7;
        int c4 = idx & 127;
        int tok = (n * TT + t) * SS + s;
        const float4* base = (const float4*)(qkv + tok * QKVC);
        ((float4*)(Ks + t * TKS))[c4] = base[384 + c4];
        ((float4*)(Vs + t * TKS))[c4] = base[640 + c4];
    }
    __syncthreads();

    const int h  = tid >> 4;
    const int tq = tid & 15;
    const int tokq = (n * TT + tq) * SS + s;

    float4 q[16];
    const float4* qb = (const float4*)(qkv + tokq * QKVC);
    #pragma unroll
    for (int i = 0; i < 16; i++) q[i] = qb[128 + h * 16 + i];

    float l[16];
    float m = -1e30f;
    #pragma unroll
    for (int kt = 0; kt < 16; kt++) {
        const float4* kp = (const float4*)(Ks + kt * TKS + h * 64);
        float dot = 0.f;
        #pragma unroll
        for (int i = 0; i < 16; i++) {
            float4 kv = kp[i];
            dot += q[i].x * kv.x + q[i].y * kv.y + q[i].z * kv.z + q[i].w * kv.w;
        }
        l[kt] = dot * SCALE;
        m = fmaxf(m, l[kt]);
    }
    float ssum = 0.f;
    #pragma unroll
    for (int kt = 0; kt < 16; kt++) { l[kt] = __expf(l[kt] - m); ssum += l[kt]; }
    float inv = 1.f / ssum;

    float4 acc[16];
    #pragma unroll
    for (int i = 0; i < 16; i++) acc[i] = make_float4(0.f, 0.f, 0.f, 0.f);
    #pragma unroll
    for (int kt = 0; kt < 16; kt++) {
        float p = l[kt] * inv;
        const float4* vp = (const float4*)(Vs + kt * TKS + h * 64);
        #pragma unroll
        for (int i = 0; i < 16; i++) {
            float4 vv = vp[i];
            acc[i].x += p * vv.x; acc[i].y += p * vv.y;
            acc[i].z += p * vv.z; acc[i].w += p * vv.w;
        }
    }

    uint2* hi4 = (uint2*)ahi;
    uint2* lo4 = (uint2*)alo;
    #pragma unroll
    for (int i = 0; i < 16; i++) {
        float vv[4] = { acc[i].x, acc[i].y, acc[i].z, acc[i].w };
        union { __nv_bfloat16 b[4]; uint2 u; } H, L;
        #pragma unroll
        for (int q4 = 0; q4 < 4; q4++) split1(vv[q4], H.b[q4], L.b[q4]);
        const int o = tokq * (DD / 4) + 128 + h * 16 + i;  // cols [512,1024)
        hi4[o] = H.u;
        lo4[o] = L.u;
    }
}

// ---------------------------------------------------------------------------
// Launch
// ---------------------------------------------------------------------------
extern "C" void kernel_launch(void* const* d_in, const int* in_sizes, int n_in,
                              void* d_out, int out_size)
{
    const float* x     = (const float*)d_in[0];   // [2,16,256,1024]
    const float* Wqkv  = (const float*)d_in[1];   // [1024, 3072]
    const float* Wproj = (const float*)d_in[2];   // [1024, 1024]
    const float* bproj = (const float*)d_in[3];   // [1024]
    float* out = (float*)d_out;

    float* qkv;
    __nv_bfloat16 *xhi, *xlo, *ahi, *alo, *wqh, *wql, *wph, *wpl;
    cudaGetSymbolAddress((void**)&qkv, g_qkv);
    cudaGetSymbolAddress((void**)&xhi, g_xhi);
    cudaGetSymbolAddress((void**)&xlo, g_xlo);
    cudaGetSymbolAddress((void**)&ahi, g_ahi);
    cudaGetSymbolAddress((void**)&alo, g_alo);
    cudaGetSymbolAddress((void**)&wqh, g_wqh);
    cudaGetSymbolAddress((void**)&wql, g_wql);
    cudaGetSymbolAddress((void**)&wph, g_wph);
    cudaGetSymbolAddress((void**)&wpl, g_wpl);

    const int spat_smem = 2 * 256 * 64 * (int)sizeof(float);   // 131072
    const int temp_smem = 2 * 16 * TKS * (int)sizeof(float);   // 66048
    cudaFuncSetAttribute(spatial_attn_kernel,
                         cudaFuncAttributeMaxDynamicSharedMemorySize, spat_smem);
    cudaFuncSetAttribute(temporal_attn_kernel,
                         cudaFuncAttributeMaxDynamicSharedMemorySize, temp_smem);

    // 0) precision splits
    const int n4x = MTOK * DD / 4;
    split_kernel<<<n4x / 256, 256>>>((const float4*)x, (uint2*)xhi, (uint2*)xlo, n4x);
    transpose_split<<<dim3(QKVC / 32, DD / 32), dim3(32, 8)>>>(Wqkv, wqh, wql, DD, QKVC);
    transpose_split<<<dim3(DD / 32, DD / 32), dim3(32, 8)>>>(Wproj, wph, wpl, DD, DD);

    // 1) qkv = x @ Wqkv   (HMMA bf16x3)
    gemm_bf16x3_mma<<<dim3(QKVC / 128, MTOK / 128), 256>>>(
        xhi, xlo, wqh, wql, qkv, MTOK, QKVC, DD, nullptr);

    // 2) attention -> ahi/alo (bf16 hi/lo, fused split)
    spatial_attn_kernel<<<NB * TT * HEADS, 256, spat_smem>>>(qkv, ahi, alo);
    temporal_attn_kernel<<<NB * SS, 128, temp_smem>>>(qkv, ahi, alo);

    // 3) out = att @ Wproj + bproj   (HMMA bf16x3)
    gemm_bf16x3_mma<<<dim3(DD / 128, MTOK / 128), 256>>>(
        ahi, alo, wph, wpl, out, MTOK, DD, DD, bproj);
}

// round 9
// speedup vs baseline: 2.2931x; 1.0142x over previous
#include <cuda_runtime.h>
#include <cuda_bf16.h>
#include <cstdint>
#include <math.h>

// Shapes (fixed by the problem)
#define NB   2
#define TT   16
#define SS   256
#define DD   1024
#define MTOK (NB*TT*SS)        // 8192 tokens
#define QKVC (3*DD)            // 3072
#define HEADS 8
#define DH    64
#define SCALE 0.125f           // (1024/16)^-0.5

// ---------------------------------------------------------------------------
// Scratch (static device allocations — no cudaMalloc anywhere)
// ---------------------------------------------------------------------------
__device__ float g_qkv[MTOK * QKVC];                        // [8192, 3072] fp32
__device__ __align__(16) __nv_bfloat16 g_xhi[MTOK * DD];
__device__ __align__(16) __nv_bfloat16 g_xlo[MTOK * DD];
__device__ __align__(16) __nv_bfloat16 g_ahi[MTOK * DD];    // attention out hi
__device__ __align__(16) __nv_bfloat16 g_alo[MTOK * DD];    // attention out lo
__device__ __align__(16) __nv_bfloat16 g_wqh[QKVC * DD];    // Wqkv^T [3072,1024]
__device__ __align__(16) __nv_bfloat16 g_wql[QKVC * DD];
__device__ __align__(16) __nv_bfloat16 g_wph[DD * DD];      // Wproj^T [1024,1024]
__device__ __align__(16) __nv_bfloat16 g_wpl[DD * DD];

// ---------------------------------------------------------------------------
// PTX helpers: mma.sync + ldmatrix + cp.async (sm_80+, safe on sm_103 target)
// ---------------------------------------------------------------------------
__device__ __forceinline__ uint32_t smem_to_u32(const void* p) {
    uint32_t a;
    asm("{ .reg .u64 t; cvta.to.shared.u64 t, %1; cvt.u32.u64 %0, t; }" : "=r"(a) : "l"(p));
    return a;
}

__device__ __forceinline__ void ldmatrix_x4(uint32_t& r0, uint32_t& r1,
                                            uint32_t& r2, uint32_t& r3, uint32_t addr) {
    asm volatile("ldmatrix.sync.aligned.m8n8.x4.shared.b16 {%0,%1,%2,%3}, [%4];"
                 : "=r"(r0), "=r"(r1), "=r"(r2), "=r"(r3) : "r"(addr));
}

__device__ __forceinline__ void mma16816(float* d, uint32_t a0, uint32_t a1,
                                         uint32_t a2, uint32_t a3,
                                         uint32_t b0, uint32_t b1) {
    asm volatile(
        "mma.sync.aligned.m16n8k16.row.col.f32.bf16.bf16.f32 "
        "{%0,%1,%2,%3}, {%4,%5,%6,%7}, {%8,%9}, {%0,%1,%2,%3};"
        : "+f"(d[0]), "+f"(d[1]), "+f"(d[2]), "+f"(d[3])
        : "r"(a0), "r"(a1), "r"(a2), "r"(a3), "r"(b0), "r"(b1));
}

__device__ __forceinline__ void cp_async16(uint32_t saddr, const void* gaddr) {
    asm volatile("cp.async.cg.shared.global [%0], [%1], 16;" :: "r"(saddr), "l"(gaddr));
}

// ---------------------------------------------------------------------------
// bf16x3 tensor-core GEMM via mma.sync: C[M,N] = A[M,K] @ B[N,K]^T (+ bias)
// CTA tile 128x128, 8 warps (warp tile 32x64), K-chunk 32.
// 2-stage cp.async double buffering (dynamic smem, 80 KB).
// SMEM rows padded to 80B -> ldmatrix phases conflict-free.
// ---------------------------------------------------------------------------
#define RS 40            // padded row stride in bf16 elems (80 bytes)
#define TILE_F (128*RS)  // bf16 elems per tile region (5120)
#define GEMM_SMEM_DYN (2 * 4 * TILE_F * 2)   // 81920 bytes

__global__ __launch_bounds__(256, 2) void gemm_bf16x3_mma(
    const __nv_bfloat16* __restrict__ Ahi, const __nv_bfloat16* __restrict__ Alo,
    const __nv_bfloat16* __restrict__ Bhi, const __nv_bfloat16* __restrict__ Blo,
    float* __restrict__ C, int M, int N, int K,
    const float* __restrict__ bias)
{
    extern __shared__ __nv_bfloat16 dsm[];  // [2 stages][4 tiles][TILE_F]

    const int tid  = threadIdx.x;
    const int wid  = tid >> 5;
    const int lane = tid & 31;
    const int warp_m = wid & 3;     // 0..3  -> 32 rows each
    const int warp_n = wid >> 2;    // 0..1  -> 64 cols each
    const int m0 = blockIdx.y * 128;
    const int n0 = blockIdx.x * 128;

    const uint32_t sbase = smem_to_u32(dsm);
    // tile base address: stage s (0/1), tile t (0=Ahi,1=Alo,2=Bhi,3=Blo)
    #define TILE_U(s, t) (sbase + (uint32_t)(((s) * 4 + (t)) * TILE_F * 2))

    float acc[2][8][4];
    #pragma unroll
    for (int i = 0; i < 2; i++)
        #pragma unroll
        for (int j = 0; j < 8; j++)
            #pragma unroll
            for (int q = 0; q < 4; q++) acc[i][j][q] = 0.f;

    // per-thread load slots: 2 uint4 per tile per chunk
    const int lr0 = tid >> 2;            // rows 0..63
    const int lc0 = tid & 3;             // col4 0..3

    const int niter = K / 32;

    // ---- prefetch chunk 0 into stage 0 ----
    {
        #pragma unroll
        for (int half = 0; half < 2; half++) {
            const int r = lr0 + half * 64;
            const uint32_t soff = (uint32_t)(r * RS + lc0 * 8) * 2;
            const size_t  aoff = (size_t)(m0 + r) * K + lc0 * 8;
            const size_t  boff = (size_t)(n0 + r) * K + lc0 * 8;
            cp_async16(TILE_U(0, 0) + soff, Ahi + aoff);
            cp_async16(TILE_U(0, 1) + soff, Alo + aoff);
            cp_async16(TILE_U(0, 2) + soff, Bhi + boff);
            cp_async16(TILE_U(0, 3) + soff, Blo + boff);
        }
        asm volatile("cp.async.commit_group;");
    }

    for (int it = 0; it < niter; it++) {
        const int stage = it & 1;

        // ---- prefetch chunk it+1 into the other stage ----
        if (it + 1 < niter) {
            const int k0n = (it + 1) * 32;
            const int sn = stage ^ 1;
            #pragma unroll
            for (int half = 0; half < 2; half++) {
                const int r = lr0 + half * 64;
                const uint32_t soff = (uint32_t)(r * RS + lc0 * 8) * 2;
                const size_t  aoff = (size_t)(m0 + r) * K + k0n + lc0 * 8;
                const size_t  boff = (size_t)(n0 + r) * K + k0n + lc0 * 8;
                cp_async16(TILE_U(sn, 0) + soff, Ahi + aoff);
                cp_async16(TILE_U(sn, 1) + soff, Alo + aoff);
                cp_async16(TILE_U(sn, 2) + soff, Bhi + boff);
                cp_async16(TILE_U(sn, 3) + soff, Blo + boff);
            }
            asm volatile("cp.async.commit_group;");
            asm volatile("cp.async.wait_group 1;");  // chunk it ready; it+1 in flight
        } else {
            asm volatile("cp.async.wait_group 0;");
        }
        __syncthreads();

        const uint32_t uAhi = TILE_U(stage, 0);
        const uint32_t uAlo = TILE_U(stage, 1);
        const uint32_t uBhi = TILE_U(stage, 2);
        const uint32_t uBlo = TILE_U(stage, 3);

        // ---- compute: 2 k16 steps ----
        #pragma unroll
        for (int ks = 0; ks < 2; ks++) {
            // A fragments (hi & lo), msub = 0,1
            uint32_t ah[2][4], al[2][4];
            const int am = (lane & 15);
            const int ak = (ks * 16 + ((lane >> 4) << 3)) * 2;  // byte offset in row
            #pragma unroll
            for (int ms = 0; ms < 2; ms++) {
                const uint32_t arow = (uint32_t)(warp_m * 32 + ms * 16 + am) * (RS * 2) + ak;
                ldmatrix_x4(ah[ms][0], ah[ms][1], ah[ms][2], ah[ms][3], uAhi + arow);
                ldmatrix_x4(al[ms][0], al[ms][1], al[ms][2], al[ms][3], uAlo + arow);
            }

            // B hi fragments: 4 x ldmatrix.x4 -> 8 n8-frags
            const int bn = (lane & 7) + ((lane >> 4) << 3);          // row within n16 pair
            const int bk = (ks * 16 + (((lane >> 3) & 1) << 3)) * 2; // byte offset
            uint32_t bh[4][4];
            #pragma unroll
            for (int nn = 0; nn < 4; nn++) {
                const uint32_t brow = (uint32_t)(warp_n * 64 + nn * 16 + bn) * (RS * 2) + bk;
                ldmatrix_x4(bh[nn][0], bh[nn][1], bh[nn][2], bh[nn][3], uBhi + brow);
            }
            // Ahi*Bhi + Alo*Bhi
            #pragma unroll
            for (int ms = 0; ms < 2; ms++)
                #pragma unroll
                for (int nn = 0; nn < 4; nn++) {
                    mma16816(acc[ms][nn * 2 + 0], ah[ms][0], ah[ms][1], ah[ms][2], ah[ms][3],
                             bh[nn][0], bh[nn][1]);
                    mma16816(acc[ms][nn * 2 + 1], ah[ms][0], ah[ms][1], ah[ms][2], ah[ms][3],
                             bh[nn][2], bh[nn][3]);
                    mma16816(acc[ms][nn * 2 + 0], al[ms][0], al[ms][1], al[ms][2], al[ms][3],
                             bh[nn][0], bh[nn][1]);
                    mma16816(acc[ms][nn * 2 + 1], al[ms][0], al[ms][1], al[ms][2], al[ms][3],
                             bh[nn][2], bh[nn][3]);
                }
            // B lo fragments (reuse bh regs) ; Ahi*Blo
            #pragma unroll
            for (int nn = 0; nn < 4; nn++) {
                const uint32_t brow = (uint32_t)(warp_n * 64 + nn * 16 + bn) * (RS * 2) + bk;
                ldmatrix_x4(bh[nn][0], bh[nn][1], bh[nn][2], bh[nn][3], uBlo + brow);
            }
            #pragma unroll
            for (int ms = 0; ms < 2; ms++)
                #pragma unroll
                for (int nn = 0; nn < 4; nn++) {
                    mma16816(acc[ms][nn * 2 + 0], ah[ms][0], ah[ms][1], ah[ms][2], ah[ms][3],
                             bh[nn][0], bh[nn][1]);
                    mma16816(acc[ms][nn * 2 + 1], ah[ms][0], ah[ms][1], ah[ms][2], ah[ms][3],
                             bh[nn][2], bh[nn][3]);
                }
        }
        __syncthreads();   // protect this stage before it is overwritten by prefetch
    }
    #undef TILE_U

    // ---- epilogue: fragment layout c0,c1 -> (row=t/4, col=(t%4)*2), c2,c3 -> row+8
    const int orow = m0 + warp_m * 32 + (lane >> 2);
    const int ocol0 = n0 + warp_n * 64 + (lane & 3) * 2;
    #pragma unroll
    for (int ms = 0; ms < 2; ms++) {
        #pragma unroll
        for (int nf = 0; nf < 8; nf++) {
            const int col = ocol0 + nf * 8;
            float b0 = 0.f, b1 = 0.f;
            if (bias) { b0 = bias[col]; b1 = bias[col + 1]; }
            float2 v0 = make_float2(acc[ms][nf][0] + b0, acc[ms][nf][1] + b1);
            float2 v1 = make_float2(acc[ms][nf][2] + b0, acc[ms][nf][3] + b1);
            *(float2*)(C + (size_t)(orow + ms * 16) * N + col) = v0;
            *(float2*)(C + (size_t)(orow + ms * 16 + 8) * N + col) = v1;
        }
    }
}

// ---------------------------------------------------------------------------
// fp32 -> bf16 hi/lo split helpers
// ---------------------------------------------------------------------------
__device__ __forceinline__ void split1(float v, __nv_bfloat16& h, __nv_bfloat16& l) {
    h = __float2bfloat16_rn(v);
    l = __float2bfloat16_rn(v - __bfloat162float(h));
}

__global__ __launch_bounds__(256) void split_kernel(
    const float4* __restrict__ in, uint2* __restrict__ hi, uint2* __restrict__ lo, int n4)
{
    int i = blockIdx.x * blockDim.x + threadIdx.x;
    if (i >= n4) return;
    float4 v = in[i];
    union { __nv_bfloat16 b[4]; uint2 u; } H, L;
    split1(v.x, H.b[0], L.b[0]);
    split1(v.y, H.b[1], L.b[1]);
    split1(v.z, H.b[2], L.b[2]);
    split1(v.w, H.b[3], L.b[3]);
    hi[i] = H.u;
    lo[i] = L.u;
}

// W [K,N] fp32 -> T [N,K] bf16 hi/lo (transpose + split)
__global__ __launch_bounds__(256) void transpose_split(
    const float* __restrict__ W,
    __nv_bfloat16* __restrict__ Thi, __nv_bfloat16* __restrict__ Tlo,
    int K, int N)
{
    __shared__ float tile[32][33];
    const int n0 = blockIdx.x * 32;
    const int k0 = blockIdx.y * 32;
    for (int i = threadIdx.y; i < 32; i += 8)
        tile[i][threadIdx.x] = W[(size_t)(k0 + i) * N + n0 + threadIdx.x];
    __syncthreads();
    for (int i = threadIdx.y; i < 32; i += 8) {
        float v = tile[threadIdx.x][i];
        __nv_bfloat16 h, l;
        split1(v, h, l);
        size_t o = (size_t)(n0 + i) * K + k0 + threadIdx.x;
        Thi[o] = h;
        Tlo[o] = l;
    }
}

// ---------------------------------------------------------------------------
// Spatial attention: writes bf16 hi/lo directly (cols [0,512) of att)
// ---------------------------------------------------------------------------
__global__ __launch_bounds__(256, 1) void spatial_attn_kernel(
    const float* __restrict__ qkv,
    __nv_bfloat16* __restrict__ ahi, __nv_bfloat16* __restrict__ alo)
{
    extern __shared__ float fsm[];
    float* Ks = fsm;
    float* Vs = fsm + 256 * 64;

    const int b = blockIdx.x;
    const int h = b & 7;
    const int t = (b >> 3) & 15;
    const int n = b >> 7;
    const int tid = threadIdx.x;
    const int frame_base = (n * TT + t) * SS;

    const float4* qkv4 = (const float4*)qkv;
    for (int idx = tid; idx < 256 * 16; idx += 256) {
        int s  = idx >> 4;
        int d4 = idx & 15;
        int base4 = (frame_base + s) * (QKVC / 4);
        ((float4*)Ks)[idx] = qkv4[base4 + 256 + h * 16 + d4];
        ((float4*)Vs)[idx] = qkv4[base4 + 512 + h * 16 + d4];
    }
    __syncthreads();

    const int s = tid;
    const int tok = frame_base + s;
    float4 q[16];
    #pragma unroll
    for (int i = 0; i < 16; i++) q[i] = qkv4[tok * (QKVC / 4) + h * 16 + i];

    float m = -1e30f, ssum = 0.f;
    float4 acc[16];
    #pragma unroll
    for (int i = 0; i < 16; i++) acc[i] = make_float4(0.f, 0.f, 0.f, 0.f);

    for (int k = 0; k < 256; k++) {
        const float4* kp = (const float4*)(Ks + k * 64);
        float dot = 0.f;
        #pragma unroll
        for (int i = 0; i < 16; i++) {
            float4 kv = kp[i];
            dot += q[i].x * kv.x + q[i].y * kv.y + q[i].z * kv.z + q[i].w * kv.w;
        }
        dot *= SCALE;
        if (dot > m) {
            float corr = __expf(m - dot);
            ssum *= corr;
            #pragma unroll
            for (int i = 0; i < 16; i++) {
                acc[i].x *= corr; acc[i].y *= corr;
                acc[i].z *= corr; acc[i].w *= corr;
            }
            m = dot;
        }
        float p = __expf(dot - m);
        ssum += p;
        const float4* vp = (const float4*)(Vs + k * 64);
        #pragma unroll
        for (int i = 0; i < 16; i++) {
            float4 vv = vp[i];
            acc[i].x += p * vv.x; acc[i].y += p * vv.y;
            acc[i].z += p * vv.z; acc[i].w += p * vv.w;
        }
    }

    float inv = 1.f / ssum;
    uint2* hi4 = (uint2*)ahi;
    uint2* lo4 = (uint2*)alo;
    #pragma unroll
    for (int i = 0; i < 16; i++) {
        float vv[4] = { acc[i].x * inv, acc[i].y * inv, acc[i].z * inv, acc[i].w * inv };
        union { __nv_bfloat16 b[4]; uint2 u; } H, L;
        #pragma unroll
        for (int q4 = 0; q4 < 4; q4++) split1(vv[q4], H.b[q4], L.b[q4]);
        const int o = tok * (DD / 4) + h * 16 + i;   // cols [0,512)
        hi4[o] = H.u;
        lo4[o] = L.u;
    }
}

// ---------------------------------------------------------------------------
// Temporal attention: writes bf16 hi/lo directly (cols [512,1024) of att)
// ---------------------------------------------------------------------------
#define TKS 516

__global__ __launch_bounds__(128, 1) void temporal_attn_kernel(
    const float* __restrict__ qkv,
    __nv_bfloat16* __restrict__ ahi, __nv_bfloat16* __restrict__ alo)
{
    extern __shared__ float fsm[];
    float* Ks = fsm;
    float* Vs = fsm + 16 * TKS;

    const int b = blockIdx.x;
    const int s = b & 255;
    const int n = b >> 8;
    const int tid = threadIdx.x;

    for (int idx = tid; idx < 16 * 128; idx += 128) {
        int t  = idx >> 7;
        int c4 = idx & 127;
        int tok = (n * TT + t) * SS + s;
        const float4* base = (const float4*)(qkv + tok * QKVC);
        ((float4*)(Ks + t * TKS))[c4] = base[384 + c4];
        ((float4*)(Vs + t * TKS))[c4] = base[640 + c4];
    }
    __syncthreads();

    const int h  = tid >> 4;
    const int tq = tid & 15;
    const int tokq = (n * TT + tq) * SS + s;

    float4 q[16];
    const float4* qb = (const float4*)(qkv + tokq * QKVC);
    #pragma unroll
    for (int i = 0; i < 16; i++) q[i] = qb[128 + h * 16 + i];

    float l[16];
    float m = -1e30f;
    #pragma unroll
    for (int kt = 0; kt < 16; kt++) {
        const float4* kp = (const float4*)(Ks + kt * TKS + h * 64);
        float dot = 0.f;
        #pragma unroll
        for (int i = 0; i < 16; i++) {
            float4 kv = kp[i];
            dot += q[i].x * kv.x + q[i].y * kv.y + q[i].z * kv.z + q[i].w * kv.w;
        }
        l[kt] = dot * SCALE;
        m = fmaxf(m, l[kt]);
    }
    float ssum = 0.f;
    #pragma unroll
    for (int kt = 0; kt < 16; kt++) { l[kt] = __expf(l[kt] - m); ssum += l[kt]; }
    float inv = 1.f / ssum;

    float4 acc[16];
    #pragma unroll
    for (int i = 0; i < 16; i++) acc[i] = make_float4(0.f, 0.f, 0.f, 0.f);
    #pragma unroll
    for (int kt = 0; kt < 16; kt++) {
        float p = l[kt] * inv;
        const float4* vp = (const float4*)(Vs + kt * TKS + h * 64);
        #pragma unroll
        for (int i = 0; i < 16; i++) {
            float4 vv = vp[i];
            acc[i].x += p * vv.x; acc[i].y += p * vv.y;
            acc[i].z += p * vv.z; acc[i].w += p * vv.w;
        }
    }

    uint2* hi4 = (uint2*)ahi;
    uint2* lo4 = (uint2*)alo;
    #pragma unroll
    for (int i = 0; i < 16; i++) {
        float vv[4] = { acc[i].x, acc[i].y, acc[i].z, acc[i].w };
        union { __nv_bfloat16 b[4]; uint2 u; } H, L;
        #pragma unroll
        for (int q4 = 0; q4 < 4; q4++) split1(vv[q4], H.b[q4], L.b[q4]);
        const int o = tokq * (DD / 4) + 128 + h * 16 + i;  // cols [512,1024)
        hi4[o] = H.u;
        lo4[o] = L.u;
    }
}

// ---------------------------------------------------------------------------
// Launch
// ---------------------------------------------------------------------------
extern "C" void kernel_launch(void* const* d_in, const int* in_sizes, int n_in,
                              void* d_out, int out_size)
{
    const float* x     = (const float*)d_in[0];   // [2,16,256,1024]
    const float* Wqkv  = (const float*)d_in[1];   // [1024, 3072]
    const float* Wproj = (const float*)d_in[2];   // [1024, 1024]
    const float* bproj = (const float*)d_in[3];   // [1024]
    float* out = (float*)d_out;

    float* qkv;
    __nv_bfloat16 *xhi, *xlo, *ahi, *alo, *wqh, *wql, *wph, *wpl;
    cudaGetSymbolAddress((void**)&qkv, g_qkv);
    cudaGetSymbolAddress((void**)&xhi, g_xhi);
    cudaGetSymbolAddress((void**)&xlo, g_xlo);
    cudaGetSymbolAddress((void**)&ahi, g_ahi);
    cudaGetSymbolAddress((void**)&alo, g_alo);
    cudaGetSymbolAddress((void**)&wqh, g_wqh);
    cudaGetSymbolAddress((void**)&wql, g_wql);
    cudaGetSymbolAddress((void**)&wph, g_wph);
    cudaGetSymbolAddress((void**)&wpl, g_wpl);

    const int spat_smem = 2 * 256 * 64 * (int)sizeof(float);   // 131072
    const int temp_smem = 2 * 16 * TKS * (int)sizeof(float);   // 66048
    cudaFuncSetAttribute(spatial_attn_kernel,
                         cudaFuncAttributeMaxDynamicSharedMemorySize, spat_smem);
    cudaFuncSetAttribute(temporal_attn_kernel,
                         cudaFuncAttributeMaxDynamicSharedMemorySize, temp_smem);
    cudaFuncSetAttribute(gemm_bf16x3_mma,
                         cudaFuncAttributeMaxDynamicSharedMemorySize, GEMM_SMEM_DYN);

    // 0) precision splits
    const int n4x = MTOK * DD / 4;
    split_kernel<<<n4x / 256, 256>>>((const float4*)x, (uint2*)xhi, (uint2*)xlo, n4x);
    transpose_split<<<dim3(QKVC / 32, DD / 32), dim3(32, 8)>>>(Wqkv, wqh, wql, DD, QKVC);
    transpose_split<<<dim3(DD / 32, DD / 32), dim3(32, 8)>>>(Wproj, wph, wpl, DD, DD);

    // 1) qkv = x @ Wqkv   (HMMA bf16x3, pipelined)
    gemm_bf16x3_mma<<<dim3(QKVC / 128, MTOK / 128), 256, GEMM_SMEM_DYN>>>(
        xhi, xlo, wqh, wql, qkv, MTOK, QKVC, DD, nullptr);

    // 2) attention -> ahi/alo (bf16 hi/lo, fused split)
    spatial_attn_kernel<<<NB * TT * HEADS, 256, spat_smem>>>(qkv, ahi, alo);
    temporal_attn_kernel<<<NB * SS, 128, temp_smem>>>(qkv, ahi, alo);

    // 3) out = att @ Wproj + bproj   (HMMA bf16x3, pipelined)
    gemm_bf16x3_mma<<<dim3(DD / 128, MTOK / 128), 256, GEMM_SMEM_DYN>>>(
        ahi, alo, wph, wpl, out, MTOK, DD, DD, bproj);
}

// round 11
// speedup vs baseline: 2.8952x; 1.2626x over previous
#include <cuda_runtime.h>
#include <cuda_fp16.h>
#include <cstdint>
#include <math.h>

// Shapes (fixed by the problem)
#define NB   2
#define TT   16
#define SS   256
#define DD   1024
#define MTOK (NB*TT*SS)        // 8192 tokens
#define QKVC (3*DD)            // 3072
#define HEADS 8
#define DH    64
#define SCALE 0.125f           // (1024/16)^-0.5

// ---------------------------------------------------------------------------
// Scratch (static device allocations — no cudaMalloc anywhere)
// ---------------------------------------------------------------------------
__device__ float g_qkv[MTOK * QKVC];                   // [8192, 3072] fp32
__device__ __align__(16) __half g_xhi[MTOK * DD];
__device__ __align__(16) __half g_xlo[MTOK * DD];
__device__ __align__(16) __half g_ahi[MTOK * DD];      // attention out hi
__device__ __align__(16) __half g_alo[MTOK * DD];      // attention out lo
__device__ __align__(16) __half g_wqh[QKVC * DD];      // Wqkv^T [3072,1024] fp16
__device__ __align__(16) __half g_wph[DD * DD];        // Wproj^T [1024,1024] fp16

// ---------------------------------------------------------------------------
// PTX helpers: mma.sync + ldmatrix + cp.async (sm_80+, safe on sm_103 target)
// ---------------------------------------------------------------------------
__device__ __forceinline__ uint32_t smem_to_u32(const void* p) {
    uint32_t a;
    asm("{ .reg .u64 t; cvta.to.shared.u64 t, %1; cvt.u32.u64 %0, t; }" : "=r"(a) : "l"(p));
    return a;
}

__device__ __forceinline__ void ldmatrix_x4(uint32_t& r0, uint32_t& r1,
                                            uint32_t& r2, uint32_t& r3, uint32_t addr) {
    asm volatile("ldmatrix.sync.aligned.m8n8.x4.shared.b16 {%0,%1,%2,%3}, [%4];"
                 : "=r"(r0), "=r"(r1), "=r"(r2), "=r"(r3) : "r"(addr));
}

__device__ __forceinline__ void mma16816(float* d, uint32_t a0, uint32_t a1,
                                         uint32_t a2, uint32_t a3,
                                         uint32_t b0, uint32_t b1) {
    asm volatile(
        "mma.sync.aligned.m16n8k16.row.col.f32.f16.f16.f32 "
        "{%0,%1,%2,%3}, {%4,%5,%6,%7}, {%8,%9}, {%0,%1,%2,%3};"
        : "+f"(d[0]), "+f"(d[1]), "+f"(d[2]), "+f"(d[3])
        : "r"(a0), "r"(a1), "r"(a2), "r"(a3), "r"(b0), "r"(b1));
}

__device__ __forceinline__ void cp_async16(uint32_t saddr, const void* gaddr) {
    asm volatile("cp.async.cg.shared.global [%0], [%1], 16;" :: "r"(saddr), "l"(gaddr));
}

// ---------------------------------------------------------------------------
// fp16x2 tensor-core GEMM: C[M,N] = (Ahi+Alo)[M,K] @ Bhi[N,K]^T (+ bias)
// Error: only B's fp16 rounding residual (~1.4e-4 rms) — A is exact to fp32.
// CTA tile 128x128, 8 warps (warp tile 32x64), K-chunk 32,
// 2-stage cp.async double buffering (3 tiles/stage, 60 KB dynamic smem).
// SMEM rows padded to 80B -> ldmatrix phases conflict-free.
// ---------------------------------------------------------------------------
#define RS 40            // padded row stride in fp16 elems (80 bytes)
#define TILE_F (128*RS)  // fp16 elems per tile region (5120)
#define GEMM_SMEM_DYN (2 * 3 * TILE_F * 2)   // 61440 bytes

__global__ __launch_bounds__(256, 2) void gemm_f16x2_mma(
    const __half* __restrict__ Ahi, const __half* __restrict__ Alo,
    const __half* __restrict__ Bhi,
    float* __restrict__ C, int M, int N, int K,
    const float* __restrict__ bias)
{
    extern __shared__ __half dsm[];  // [2 stages][3 tiles][TILE_F]

    const int tid  = threadIdx.x;
    const int wid  = tid >> 5;
    const int lane = tid & 31;
    const int warp_m = wid & 3;     // 0..3  -> 32 rows each
    const int warp_n = wid >> 2;    // 0..1  -> 64 cols each
    const int m0 = blockIdx.y * 128;
    const int n0 = blockIdx.x * 128;

    const uint32_t sbase = smem_to_u32(dsm);
    // tile base address: stage s (0/1), tile t (0=Ahi,1=Alo,2=Bhi)
    #define TILE_U(s, t) (sbase + (uint32_t)(((s) * 3 + (t)) * TILE_F * 2))

    float acc[2][8][4];
    #pragma unroll
    for (int i = 0; i < 2; i++)
        #pragma unroll
        for (int j = 0; j < 8; j++)
            #pragma unroll
            for (int q = 0; q < 4; q++) acc[i][j][q] = 0.f;

    // per-thread load slots: 2 uint4 per tile per chunk
    const int lr0 = tid >> 2;            // rows 0..63
    const int lc0 = tid & 3;             // col4 0..3

    const int niter = K / 32;

    // ---- prefetch chunk 0 into stage 0 ----
    {
        #pragma unroll
        for (int half = 0; half < 2; half++) {
            const int r = lr0 + half * 64;
            const uint32_t soff = (uint32_t)(r * RS + lc0 * 8) * 2;
            const size_t  aoff = (size_t)(m0 + r) * K + lc0 * 8;
            const size_t  boff = (size_t)(n0 + r) * K + lc0 * 8;
            cp_async16(TILE_U(0, 0) + soff, Ahi + aoff);
            cp_async16(TILE_U(0, 1) + soff, Alo + aoff);
            cp_async16(TILE_U(0, 2) + soff, Bhi + boff);
        }
        asm volatile("cp.async.commit_group;");
    }

    for (int it = 0; it < niter; it++) {
        const int stage = it & 1;

        // ---- prefetch chunk it+1 into the other stage ----
        if (it + 1 < niter) {
            const int k0n = (it + 1) * 32;
            const int sn = stage ^ 1;
            #pragma unroll
            for (int half = 0; half < 2; half++) {
                const int r = lr0 + half * 64;
                const uint32_t soff = (uint32_t)(r * RS + lc0 * 8) * 2;
                const size_t  aoff = (size_t)(m0 + r) * K + k0n + lc0 * 8;
                const size_t  boff = (size_t)(n0 + r) * K + k0n + lc0 * 8;
                cp_async16(TILE_U(sn, 0) + soff, Ahi + aoff);
                cp_async16(TILE_U(sn, 1) + soff, Alo + aoff);
                cp_async16(TILE_U(sn, 2) + soff, Bhi + boff);
            }
            asm volatile("cp.async.commit_group;");
            asm volatile("cp.async.wait_group 1;");  // chunk it ready; it+1 in flight
        } else {
            asm volatile("cp.async.wait_group 0;");
        }
        __syncthreads();

        const uint32_t uAhi = TILE_U(stage, 0);
        const uint32_t uAlo = TILE_U(stage, 1);
        const uint32_t uBhi = TILE_U(stage, 2);

        // ---- compute: 2 k16 steps ----
        #pragma unroll
        for (int ks = 0; ks < 2; ks++) {
            // A fragments (hi & lo), msub = 0,1
            uint32_t ah[2][4], al[2][4];
            const int am = (lane & 15);
            const int ak = (ks * 16 + ((lane >> 4) << 3)) * 2;  // byte offset in row
            #pragma unroll
            for (int ms = 0; ms < 2; ms++) {
                const uint32_t arow = (uint32_t)(warp_m * 32 + ms * 16 + am) * (RS * 2) + ak;
                ldmatrix_x4(ah[ms][0], ah[ms][1], ah[ms][2], ah[ms][3], uAhi + arow);
                ldmatrix_x4(al[ms][0], al[ms][1], al[ms][2], al[ms][3], uAlo + arow);
            }

            // B hi fragments: 4 x ldmatrix.x4 -> 8 n8-frags
            const int bn = (lane & 7) + ((lane >> 4) << 3);          // row within n16 pair
            const int bk = (ks * 16 + (((lane >> 3) & 1) << 3)) * 2; // byte offset
            uint32_t bh[4][4];
            #pragma unroll
            for (int nn = 0; nn < 4; nn++) {
                const uint32_t brow = (uint32_t)(warp_n * 64 + nn * 16 + bn) * (RS * 2) + bk;
                ldmatrix_x4(bh[nn][0], bh[nn][1], bh[nn][2], bh[nn][3], uBhi + brow);
            }
            // (Ahi + Alo) * Bhi
            #pragma unroll
            for (int ms = 0; ms < 2; ms++)
                #pragma unroll
                for (int nn = 0; nn < 4; nn++) {
                    mma16816(acc[ms][nn * 2 + 0], ah[ms][0], ah[ms][1], ah[ms][2], ah[ms][3],
                             bh[nn][0], bh[nn][1]);
                    mma16816(acc[ms][nn * 2 + 1], ah[ms][0], ah[ms][1], ah[ms][2], ah[ms][3],
                             bh[nn][2], bh[nn][3]);
                    mma16816(acc[ms][nn * 2 + 0], al[ms][0], al[ms][1], al[ms][2], al[ms][3],
                             bh[nn][0], bh[nn][1]);
                    mma16816(acc[ms][nn * 2 + 1], al[ms][0], al[ms][1], al[ms][2], al[ms][3],
                             bh[nn][2], bh[nn][3]);
                }
        }
        __syncthreads();   // protect this stage before it is overwritten by prefetch
    }
    #undef TILE_U

    // ---- epilogue: fragment layout c0,c1 -> (row=t/4, col=(t%4)*2), c2,c3 -> row+8
    const int orow = m0 + warp_m * 32 + (lane >> 2);
    const int ocol0 = n0 + warp_n * 64 + (lane & 3) * 2;
    #pragma unroll
    for (int ms = 0; ms < 2; ms++) {
        #pragma unroll
        for (int nf = 0; nf < 8; nf++) {
            const int col = ocol0 + nf * 8;
            float b0 = 0.f, b1 = 0.f;
            if (bias) { b0 = bias[col]; b1 = bias[col + 1]; }
            float2 v0 = make_float2(acc[ms][nf][0] + b0, acc[ms][nf][1] + b1);
            float2 v1 = make_float2(acc[ms][nf][2] + b0, acc[ms][nf][3] + b1);
            *(float2*)(C + (size_t)(orow + ms * 16) * N + col) = v0;
            *(float2*)(C + (size_t)(orow + ms * 16 + 8) * N + col) = v1;
        }
    }
}

// ---------------------------------------------------------------------------
// fp32 -> fp16 hi/lo split helpers
// ---------------------------------------------------------------------------
__device__ __forceinline__ void split1(float v, __half& h, __half& l) {
    h = __float2half_rn(v);
    l = __float2half_rn(v - __half2float(h));
}

__global__ __launch_bounds__(256) void split_kernel(
    const float4* __restrict__ in, uint2* __restrict__ hi, uint2* __restrict__ lo, int n4)
{
    int i = blockIdx.x * blockDim.x + threadIdx.x;
    if (i >= n4) return;
    float4 v = in[i];
    union { __half b[4]; uint2 u; } H, L;
    split1(v.x, H.b[0], L.b[0]);
    split1(v.y, H.b[1], L.b[1]);
    split1(v.z, H.b[2], L.b[2]);
    split1(v.w, H.b[3], L.b[3]);
    hi[i] = H.u;
    lo[i] = L.u;
}

// W [K,N] fp32 -> T [N,K] fp16 (transpose + round)
__global__ __launch_bounds__(256) void transpose_h(
    const float* __restrict__ W, __half* __restrict__ T, int K, int N)
{
    __shared__ float tile[32][33];
    const int n0 = blockIdx.x * 32;
    const int k0 = blockIdx.y * 32;
    for (int i = threadIdx.y; i < 32; i += 8)
        tile[i][threadIdx.x] = W[(size_t)(k0 + i) * N + n0 + threadIdx.x];
    __syncthreads();
    for (int i = threadIdx.y; i < 32; i += 8) {
        float v = tile[threadIdx.x][i];
        T[(size_t)(n0 + i) * K + k0 + threadIdx.x] = __float2half_rn(v);
    }
}

// ---------------------------------------------------------------------------
// Spatial attention: writes fp16 hi/lo directly (cols [0,512) of att)
// ---------------------------------------------------------------------------
__global__ __launch_bounds__(256, 1) void spatial_attn_kernel(
    const float* __restrict__ qkv,
    __half* __restrict__ ahi, __half* __restrict__ alo)
{
    extern __shared__ float fsm[];
    float* Ks = fsm;
    float* Vs = fsm + 256 * 64;

    const int b = blockIdx.x;
    const int h = b & 7;
    const int t = (b >> 3) & 15;
    const int n = b >> 7;
    const int tid = threadIdx.x;
    const int frame_base = (n * TT + t) * SS;

    const float4* qkv4 = (const float4*)qkv;
    for (int idx = tid; idx < 256 * 16; idx += 256) {
        int s  = idx >> 4;
        int d4 = idx & 15;
        int base4 = (frame_base + s) * (QKVC / 4);
        ((float4*)Ks)[idx] = qkv4[base4 + 256 + h * 16 + d4];
        ((float4*)Vs)[idx] = qkv4[base4 + 512 + h * 16 + d4];
    }
    __syncthreads();

    const int s = tid;
    const int tok = frame_base + s;
    float4 q[16];
    #pragma unroll
    for (int i = 0; i < 16; i++) q[i] = qkv4[tok * (QKVC / 4) + h * 16 + i];

    float m = -1e30f, ssum = 0.f;
    float4 acc[16];
    #pragma unroll
    for (int i = 0; i < 16; i++) acc[i] = make_float4(0.f, 0.f, 0.f, 0.f);

    for (int k = 0; k < 256; k++) {
        const float4* kp = (const float4*)(Ks + k * 64);
        float dot = 0.f;
        #pragma unroll
        for (int i = 0; i < 16; i++) {
            float4 kv = kp[i];
            dot += q[i].x * kv.x + q[i].y * kv.y + q[i].z * kv.z + q[i].w * kv.w;
        }
        dot *= SCALE;
        if (dot > m) {
            float corr = __expf(m - dot);
            ssum *= corr;
            #pragma unroll
            for (int i = 0; i < 16; i++) {
                acc[i].x *= corr; acc[i].y *= corr;
                acc[i].z *= corr; acc[i].w *= corr;
            }
            m = dot;
        }
        float p = __expf(dot - m);
        ssum += p;
        const float4* vp = (const float4*)(Vs + k * 64);
        #pragma unroll
        for (int i = 0; i < 16; i++) {
            float4 vv = vp[i];
            acc[i].x += p * vv.x; acc[i].y += p * vv.y;
            acc[i].z += p * vv.z; acc[i].w += p * vv.w;
        }
    }

    float inv = 1.f / ssum;
    uint2* hi4 = (uint2*)ahi;
    uint2* lo4 = (uint2*)alo;
    #pragma unroll
    for (int i = 0; i < 16; i++) {
        float vv[4] = { acc[i].x * inv, acc[i].y * inv, acc[i].z * inv, acc[i].w * inv };
        union { __half b[4]; uint2 u; } H, L;
        #pragma unroll
        for (int q4 = 0; q4 < 4; q4++) split1(vv[q4], H.b[q4], L.b[q4]);
        const int o = tok * (DD / 4) + h * 16 + i;   // cols [0,512)
        hi4[o] = H.u;
        lo4[o] = L.u;
    }
}

// ---------------------------------------------------------------------------
// Temporal attention: writes fp16 hi/lo directly (cols [512,1024) of att)
// ---------------------------------------------------------------------------
#define TKS 516

__global__ __launch_bounds__(128, 1) void temporal_attn_kernel(
    const float* __restrict__ qkv,
    __half* __restrict__ ahi, __half* __restrict__ alo)
{
    extern __shared__ float fsm[];
    float* Ks = fsm;
    float* Vs = fsm + 16 * TKS;

    const int b = blockIdx.x;
    const int s = b & 255;
    const int n = b >> 8;
    const int tid = threadIdx.x;

    for (int idx = tid; idx < 16 * 128; idx += 128) {
        int t  = idx >> 7;
        int c4 = idx & 127;
        int tok = (n * TT + t) * SS + s;
        const float4* base = (const float4*)(qkv + tok * QKVC);
        ((float4*)(Ks + t * TKS))[c4] = base[384 + c4];
        ((float4*)(Vs + t * TKS))[c4] = base[640 + c4];
    }
    __syncthreads();

    const int h  = tid >> 4;
    const int tq = tid & 15;
    const int tokq = (n * TT + tq) * SS + s;

    float4 q[16];
    const float4* qb = (const float4*)(qkv + tokq * QKVC);
    #pragma unroll
    for (int i = 0; i < 16; i++) q[i] = qb[128 + h * 16 + i];

    float l[16];
    float m = -1e30f;
    #pragma unroll
    for (int kt = 0; kt < 16; kt++) {
        const float4* kp = (const float4*)(Ks + kt * TKS + h * 64);
        float dot = 0.f;
        #pragma unroll
        for (int i = 0; i < 16; i++) {
            float4 kv = kp[i];
            dot += q[i].x * kv.x + q[i].y * kv.y + q[i].z * kv.z + q[i].w * kv.w;
        }
        l[kt] = dot * SCALE;
        m = fmaxf(m, l[kt]);
    }
    float ssum = 0.f;
    #pragma unroll
    for (int kt = 0; kt < 16; kt++) { l[kt] = __expf(l[kt] - m); ssum += l[kt]; }
    float inv = 1.f / ssum;

    float4 acc[16];
    #pragma unroll
    for (int i = 0; i < 16; i++) acc[i] = make_float4(0.f, 0.f, 0.f, 0.f);
    #pragma unroll
    for (int kt = 0; kt < 16; kt++) {
        float p = l[kt] * inv;
        const float4* vp = (const float4*)(Vs + kt * TKS + h * 64);
        #pragma unroll
        for (int i = 0; i < 16; i++) {
            float4 vv = vp[i];
            acc[i].x += p * vv.x; acc[i].y += p * vv.y;
            acc[i].z += p * vv.z; acc[i].w += p * vv.w;
        }
    }

    uint2* hi4 = (uint2*)ahi;
    uint2* lo4 = (uint2*)alo;
    #pragma unroll
    for (int i = 0; i < 16; i++) {
        float vv[4] = { acc[i].x, acc[i].y, acc[i].z, acc[i].w };
        union { __half b[4]; uint2 u; } H, L;
        #pragma unroll
        for (int q4 = 0; q4 < 4; q4++) split1(vv[q4], H.b[q4], L.b[q4]);
        const int o = tokq * (DD / 4) + 128 + h * 16 + i;  // cols [512,1024)
        hi4[o] = H.u;
        lo4[o] = L.u;
    }
}

// ---------------------------------------------------------------------------
// Launch
// ---------------------------------------------------------------------------
extern "C" void kernel_launch(void* const* d_in, const int* in_sizes, int n_in,
                              void* d_out, int out_size)
{
    const float* x     = (const float*)d_in[0];   // [2,16,256,1024]
    const float* Wqkv  = (const float*)d_in[1];   // [1024, 3072]
    const float* Wproj = (const float*)d_in[2];   // [1024, 1024]
    const float* bproj = (const float*)d_in[3];   // [1024]
    float* out = (float*)d_out;

    float* qkv;
    __half *xhi, *xlo, *ahi, *alo, *wqh, *wph;
    cudaGetSymbolAddress((void**)&qkv, g_qkv);
    cudaGetSymbolAddress((void**)&xhi, g_xhi);
    cudaGetSymbolAddress((void**)&xlo, g_xlo);
    cudaGetSymbolAddress((void**)&ahi, g_ahi);
    cudaGetSymbolAddress((void**)&alo, g_alo);
    cudaGetSymbolAddress((void**)&wqh, g_wqh);
    cudaGetSymbolAddress((void**)&wph, g_wph);

    const int spat_smem = 2 * 256 * 64 * (int)sizeof(float);   // 131072
    const int temp_smem = 2 * 16 * TKS * (int)sizeof(float);   // 66048
    cudaFuncSetAttribute(spatial_attn_kernel,
                         cudaFuncAttributeMaxDynamicSharedMemorySize, spat_smem);
    cudaFuncSetAttribute(temporal_attn_kernel,
                         cudaFuncAttributeMaxDynamicSharedMemorySize, temp_smem);
    cudaFuncSetAttribute(gemm_f16x2_mma,
                         cudaFuncAttributeMaxDynamicSharedMemorySize, GEMM_SMEM_DYN);

    // 0) precision splits / weight transposes (fp16)
    const int n4x = MTOK * DD / 4;
    split_kernel<<<n4x / 256, 256>>>((const float4*)x, (uint2*)xhi, (uint2*)xlo, n4x);
    transpose_h<<<dim3(QKVC / 32, DD / 32), dim3(32, 8)>>>(Wqkv, wqh, DD, QKVC);
    transpose_h<<<dim3(DD / 32, DD / 32), dim3(32, 8)>>>(Wproj, wph, DD, DD);

    // 1) qkv = x @ Wqkv   (HMMA fp16 2-product)
    gemm_f16x2_mma<<<dim3(QKVC / 128, MTOK / 128), 256, GEMM_SMEM_DYN>>>(
        xhi, xlo, wqh, qkv, MTOK, QKVC, DD, nullptr);

    // 2) attention -> ahi/alo (fp16 hi/lo, fused split)
    spatial_attn_kernel<<<NB * TT * HEADS, 256, spat_smem>>>(qkv, ahi, alo);
    temporal_attn_kernel<<<NB * SS, 128, temp_smem>>>(qkv, ahi, alo);

    // 3) out = att @ Wproj + bproj   (HMMA fp16 2-product)
    gemm_f16x2_mma<<<dim3(DD / 128, MTOK / 128), 256, GEMM_SMEM_DYN>>>(
        ahi, alo, wph, out, MTOK, DD, DD, bproj);
}

// round 12
// speedup vs baseline: 3.9628x; 1.3687x over previous
#include <cuda_runtime.h>
#include <cuda_fp16.h>
#include <cstdint>
#include <math.h>

// Shapes (fixed by the problem)
#define NB   2
#define TT   16
#define SS   256
#define DD   1024
#define MTOK (NB*TT*SS)        // 8192 tokens
#define QKVC (3*DD)            // 3072
#define HEADS 8
#define DH    64
#define SCALE 0.125f           // (1024/16)^-0.5

// ---------------------------------------------------------------------------
// Scratch (static device allocations — no cudaMalloc anywhere)
// ---------------------------------------------------------------------------
__device__ float g_qkv[MTOK * QKVC];                   // [8192, 3072] fp32
__device__ __align__(16) __half g_xh[MTOK * DD];       // x in fp16
__device__ __align__(16) __half g_ah[MTOK * DD];       // attention out fp16
__device__ __align__(16) __half g_wqh[QKVC * DD];      // Wqkv^T [3072,1024] fp16
__device__ __align__(16) __half g_wph[DD * DD];        // Wproj^T [1024,1024] fp16

// ---------------------------------------------------------------------------
// PTX helpers: mma.sync + ldmatrix + cp.async (sm_80+, safe on sm_103 target)
// ---------------------------------------------------------------------------
__device__ __forceinline__ uint32_t smem_to_u32(const void* p) {
    uint32_t a;
    asm("{ .reg .u64 t; cvta.to.shared.u64 t, %1; cvt.u32.u64 %0, t; }" : "=r"(a) : "l"(p));
    return a;
}

__device__ __forceinline__ void ldmatrix_x4(uint32_t& r0, uint32_t& r1,
                                            uint32_t& r2, uint32_t& r3, uint32_t addr) {
    asm volatile("ldmatrix.sync.aligned.m8n8.x4.shared.b16 {%0,%1,%2,%3}, [%4];"
                 : "=r"(r0), "=r"(r1), "=r"(r2), "=r"(r3) : "r"(addr));
}

__device__ __forceinline__ void mma16816(float* d, uint32_t a0, uint32_t a1,
                                         uint32_t a2, uint32_t a3,
                                         uint32_t b0, uint32_t b1) {
    asm volatile(
        "mma.sync.aligned.m16n8k16.row.col.f32.f16.f16.f32 "
        "{%0,%1,%2,%3}, {%4,%5,%6,%7}, {%8,%9}, {%0,%1,%2,%3};"
        : "+f"(d[0]), "+f"(d[1]), "+f"(d[2]), "+f"(d[3])
        : "r"(a0), "r"(a1), "r"(a2), "r"(a3), "r"(b0), "r"(b1));
}

__device__ __forceinline__ void cp_async16(uint32_t saddr, const void* gaddr) {
    asm volatile("cp.async.cg.shared.global [%0], [%1], 16;" :: "r"(saddr), "l"(gaddr));
}

// ---------------------------------------------------------------------------
// fp16 tensor-core GEMM: C[M,N] = A[M,K] @ B[N,K]^T (+ bias), fp32 accumulate.
// CTA tile 128x128, 8 warps (warp tile 32x64), K-chunk 32,
// 2-stage cp.async double buffering (2 tiles/stage, 40 KB dynamic smem).
// SMEM rows padded to 80B -> ldmatrix phases conflict-free.
// ---------------------------------------------------------------------------
#define RS 40            // padded row stride in fp16 elems (80 bytes)
#define TILE_F (128*RS)  // fp16 elems per tile region (5120)
#define GEMM_SMEM_DYN (2 * 2 * TILE_F * 2)   // 40960 bytes

__global__ __launch_bounds__(256, 2) void gemm_f16_mma(
    const __half* __restrict__ A, const __half* __restrict__ B,
    float* __restrict__ C, int M, int N, int K,
    const float* __restrict__ bias)
{
    extern __shared__ __half dsm[];  // [2 stages][2 tiles][TILE_F]

    const int tid  = threadIdx.x;
    const int wid  = tid >> 5;
    const int lane = tid & 31;
    const int warp_m = wid & 3;     // 0..3  -> 32 rows each
    const int warp_n = wid >> 2;    // 0..1  -> 64 cols each
    const int m0 = blockIdx.y * 128;
    const int n0 = blockIdx.x * 128;

    const uint32_t sbase = smem_to_u32(dsm);
    // tile base address: stage s (0/1), tile t (0=A,1=B)
    #define TILE_U(s, t) (sbase + (uint32_t)(((s) * 2 + (t)) * TILE_F * 2))

    float acc[2][8][4];
    #pragma unroll
    for (int i = 0; i < 2; i++)
        #pragma unroll
        for (int j = 0; j < 8; j++)
            #pragma unroll
            for (int q = 0; q < 4; q++) acc[i][j][q] = 0.f;

    // per-thread load slots: 2 uint4 per tile per chunk
    const int lr0 = tid >> 2;            // rows 0..63
    const int lc0 = tid & 3;             // col4 0..3

    const int niter = K / 32;

    // ---- prefetch chunk 0 into stage 0 ----
    {
        #pragma unroll
        for (int half = 0; half < 2; half++) {
            const int r = lr0 + half * 64;
            const uint32_t soff = (uint32_t)(r * RS + lc0 * 8) * 2;
            cp_async16(TILE_U(0, 0) + soff, A + (size_t)(m0 + r) * K + lc0 * 8);
            cp_async16(TILE_U(0, 1) + soff, B + (size_t)(n0 + r) * K + lc0 * 8);
        }
        asm volatile("cp.async.commit_group;");
    }

    for (int it = 0; it < niter; it++) {
        const int stage = it & 1;

        // ---- prefetch chunk it+1 into the other stage ----
        if (it + 1 < niter) {
            const int k0n = (it + 1) * 32;
            const int sn = stage ^ 1;
            #pragma unroll
            for (int half = 0; half < 2; half++) {
                const int r = lr0 + half * 64;
                const uint32_t soff = (uint32_t)(r * RS + lc0 * 8) * 2;
                cp_async16(TILE_U(sn, 0) + soff, A + (size_t)(m0 + r) * K + k0n + lc0 * 8);
                cp_async16(TILE_U(sn, 1) + soff, B + (size_t)(n0 + r) * K + k0n + lc0 * 8);
            }
            asm volatile("cp.async.commit_group;");
            asm volatile("cp.async.wait_group 1;");  // chunk it ready; it+1 in flight
        } else {
            asm volatile("cp.async.wait_group 0;");
        }
        __syncthreads();

        const uint32_t uA = TILE_U(stage, 0);
        const uint32_t uB = TILE_U(stage, 1);

        // ---- compute: 2 k16 steps ----
        #pragma unroll
        for (int ks = 0; ks < 2; ks++) {
            uint32_t ah[2][4];
            const int am = (lane & 15);
            const int ak = (ks * 16 + ((lane >> 4) << 3)) * 2;  // byte offset in row
            #pragma unroll
            for (int ms = 0; ms < 2; ms++) {
                const uint32_t arow = (uint32_t)(warp_m * 32 + ms * 16 + am) * (RS * 2) + ak;
                ldmatrix_x4(ah[ms][0], ah[ms][1], ah[ms][2], ah[ms][3], uA + arow);
            }

            const int bn = (lane & 7) + ((lane >> 4) << 3);          // row within n16 pair
            const int bk = (ks * 16 + (((lane >> 3) & 1) << 3)) * 2; // byte offset
            uint32_t bh[4][4];
            #pragma unroll
            for (int nn = 0; nn < 4; nn++) {
                const uint32_t brow = (uint32_t)(warp_n * 64 + nn * 16 + bn) * (RS * 2) + bk;
                ldmatrix_x4(bh[nn][0], bh[nn][1], bh[nn][2], bh[nn][3], uB + brow);
            }
            #pragma unroll
            for (int ms = 0; ms < 2; ms++)
                #pragma unroll
                for (int nn = 0; nn < 4; nn++) {
                    mma16816(acc[ms][nn * 2 + 0], ah[ms][0], ah[ms][1], ah[ms][2], ah[ms][3],
                             bh[nn][0], bh[nn][1]);
                    mma16816(acc[ms][nn * 2 + 1], ah[ms][0], ah[ms][1], ah[ms][2], ah[ms][3],
                             bh[nn][2], bh[nn][3]);
                }
        }
        __syncthreads();   // protect this stage before it is overwritten by prefetch
    }
    #undef TILE_U

    // ---- epilogue: fragment layout c0,c1 -> (row=t/4, col=(t%4)*2), c2,c3 -> row+8
    const int orow = m0 + warp_m * 32 + (lane >> 2);
    const int ocol0 = n0 + warp_n * 64 + (lane & 3) * 2;
    #pragma unroll
    for (int ms = 0; ms < 2; ms++) {
        #pragma unroll
        for (int nf = 0; nf < 8; nf++) {
            const int col = ocol0 + nf * 8;
            float b0 = 0.f, b1 = 0.f;
            if (bias) { b0 = bias[col]; b1 = bias[col + 1]; }
            float2 v0 = make_float2(acc[ms][nf][0] + b0, acc[ms][nf][1] + b1);
            float2 v1 = make_float2(acc[ms][nf][2] + b0, acc[ms][nf][3] + b1);
            *(float2*)(C + (size_t)(orow + ms * 16) * N + col) = v0;
            *(float2*)(C + (size_t)(orow + ms * 16 + 8) * N + col) = v1;
        }
    }
}

// ---------------------------------------------------------------------------
// fp32 -> fp16 convert / transpose
// ---------------------------------------------------------------------------
__global__ __launch_bounds__(256) void convert_h(
    const float4* __restrict__ in, uint2* __restrict__ outh, int n4)
{
    int i = blockIdx.x * blockDim.x + threadIdx.x;
    if (i >= n4) return;
    float4 v = in[i];
    union { __half b[4]; uint2 u; } H;
    H.b[0] = __float2half_rn(v.x);
    H.b[1] = __float2half_rn(v.y);
    H.b[2] = __float2half_rn(v.z);
    H.b[3] = __float2half_rn(v.w);
    outh[i] = H.u;
}

// W [K,N] fp32 -> T [N,K] fp16 (transpose + round)
__global__ __launch_bounds__(256) void transpose_h(
    const float* __restrict__ W, __half* __restrict__ T, int K, int N)
{
    __shared__ float tile[32][33];
    const int n0 = blockIdx.x * 32;
    const int k0 = blockIdx.y * 32;
    for (int i = threadIdx.y; i < 32; i += 8)
        tile[i][threadIdx.x] = W[(size_t)(k0 + i) * N + n0 + threadIdx.x];
    __syncthreads();
    for (int i = threadIdx.y; i < 32; i += 8) {
        float v = tile[threadIdx.x][i];
        T[(size_t)(n0 + i) * K + k0 + threadIdx.x] = __float2half_rn(v);
    }
}

// ---------------------------------------------------------------------------
// Spatial attention: writes fp16 directly (cols [0,512) of att)
// ---------------------------------------------------------------------------
__global__ __launch_bounds__(256, 1) void spatial_attn_kernel(
    const float* __restrict__ qkv, __half* __restrict__ ah)
{
    extern __shared__ float fsm[];
    float* Ks = fsm;
    float* Vs = fsm + 256 * 64;

    const int b = blockIdx.x;
    const int h = b & 7;
    const int t = (b >> 3) & 15;
    const int n = b >> 7;
    const int tid = threadIdx.x;
    const int frame_base = (n * TT + t) * SS;

    const float4* qkv4 = (const float4*)qkv;
    for (int idx = tid; idx < 256 * 16; idx += 256) {
        int s  = idx >> 4;
        int d4 = idx & 15;
        int base4 = (frame_base + s) * (QKVC / 4);
        ((float4*)Ks)[idx] = qkv4[base4 + 256 + h * 16 + d4];
        ((float4*)Vs)[idx] = qkv4[base4 + 512 + h * 16 + d4];
    }
    __syncthreads();

    const int s = tid;
    const int tok = frame_base + s;
    float4 q[16];
    #pragma unroll
    for (int i = 0; i < 16; i++) q[i] = qkv4[tok * (QKVC / 4) + h * 16 + i];

    float m = -1e30f, ssum = 0.f;
    float4 acc[16];
    #pragma unroll
    for (int i = 0; i < 16; i++) acc[i] = make_float4(0.f, 0.f, 0.f, 0.f);

    for (int k = 0; k < 256; k++) {
        const float4* kp = (const float4*)(Ks + k * 64);
        float dot = 0.f;
        #pragma unroll
        for (int i = 0; i < 16; i++) {
            float4 kv = kp[i];
            dot += q[i].x * kv.x + q[i].y * kv.y + q[i].z * kv.z + q[i].w * kv.w;
        }
        dot *= SCALE;
        if (dot > m) {
            float corr = __expf(m - dot);
            ssum *= corr;
            #pragma unroll
            for (int i = 0; i < 16; i++) {
                acc[i].x *= corr; acc[i].y *= corr;
                acc[i].z *= corr; acc[i].w *= corr;
            }
            m = dot;
        }
        float p = __expf(dot - m);
        ssum += p;
        const float4* vp = (const float4*)(Vs + k * 64);
        #pragma unroll
        for (int i = 0; i < 16; i++) {
            float4 vv = vp[i];
            acc[i].x += p * vv.x; acc[i].y += p * vv.y;
            acc[i].z += p * vv.z; acc[i].w += p * vv.w;
        }
    }

    float inv = 1.f / ssum;
    uint2* out4 = (uint2*)ah;
    #pragma unroll
    for (int i = 0; i < 16; i++) {
        union { __half b[4]; uint2 u; } H;
        H.b[0] = __float2half_rn(acc[i].x * inv);
        H.b[1] = __float2half_rn(acc[i].y * inv);
        H.b[2] = __float2half_rn(acc[i].z * inv);
        H.b[3] = __float2half_rn(acc[i].w * inv);
        out4[tok * (DD / 4) + h * 16 + i] = H.u;   // cols [0,512)
    }
}

// ---------------------------------------------------------------------------
// Temporal attention: writes fp16 directly (cols [512,1024) of att)
// ---------------------------------------------------------------------------
#define TKS 516

__global__ __launch_bounds__(128, 1) void temporal_attn_kernel(
    const float* __restrict__ qkv, __half* __restrict__ ah)
{
    extern __shared__ float fsm[];
    float* Ks = fsm;
    float* Vs = fsm + 16 * TKS;

    const int b = blockIdx.x;
    const int s = b & 255;
    const int n = b >> 8;
    const int tid = threadIdx.x;

    for (int idx = tid; idx < 16 * 128; idx += 128) {
        int t  = idx >> 7;
        int c4 = idx & 127;
        int tok = (n * TT + t) * SS + s;
        const float4* base = (const float4*)(qkv + tok * QKVC);
        ((float4*)(Ks + t * TKS))[c4] = base[384 + c4];
        ((float4*)(Vs + t * TKS))[c4] = base[640 + c4];
    }
    __syncthreads();

    const int h  = tid >> 4;
    const int tq = tid & 15;
    const int tokq = (n * TT + tq) * SS + s;

    float4 q[16];
    const float4* qb = (const float4*)(qkv + tokq * QKVC);
    #pragma unroll
    for (int i = 0; i < 16; i++) q[i] = qb[128 + h * 16 + i];

    float l[16];
    float m = -1e30f;
    #pragma unroll
    for (int kt = 0; kt < 16; kt++) {
        const float4* kp = (const float4*)(Ks + kt * TKS + h * 64);
        float dot = 0.f;
        #pragma unroll
        for (int i = 0; i < 16; i++) {
            float4 kv = kp[i];
            dot += q[i].x * kv.x + q[i].y * kv.y + q[i].z * kv.z + q[i].w * kv.w;
        }
        l[kt] = dot * SCALE;
        m = fmaxf(m, l[kt]);
    }
    float ssum = 0.f;
    #pragma unroll
    for (int kt = 0; kt < 16; kt++) { l[kt] = __expf(l[kt] - m); ssum += l[kt]; }
    float inv = 1.f / ssum;

    float4 acc[16];
    #pragma unroll
    for (int i = 0; i < 16; i++) acc[i] = make_float4(0.f, 0.f, 0.f, 0.f);
    #pragma unroll
    for (int kt = 0; kt < 16; kt++) {
        float p = l[kt] * inv;
        const float4* vp = (const float4*)(Vs + kt * TKS + h * 64);
        #pragma unroll
        for (int i = 0; i < 16; i++) {
            float4 vv = vp[i];
            acc[i].x += p * vv.x; acc[i].y += p * vv.y;
            acc[i].z += p * vv.z; acc[i].w += p * vv.w;
        }
    }

    uint2* out4 = (uint2*)ah;
    #pragma unroll
    for (int i = 0; i < 16; i++) {
        union { __half b[4]; uint2 u; } H;
        H.b[0] = __float2half_rn(acc[i].x);
        H.b[1] = __float2half_rn(acc[i].y);
        H.b[2] = __float2half_rn(acc[i].z);
        H.b[3] = __float2half_rn(acc[i].w);
        out4[tokq * (DD / 4) + 128 + h * 16 + i] = H.u;  // cols [512,1024)
    }
}

// ---------------------------------------------------------------------------
// Launch
// ---------------------------------------------------------------------------
extern "C" void kernel_launch(void* const* d_in, const int* in_sizes, int n_in,
                              void* d_out, int out_size)
{
    const float* x     = (const float*)d_in[0];   // [2,16,256,1024]
    const float* Wqkv  = (const float*)d_in[1];   // [1024, 3072]
    const float* Wproj = (const float*)d_in[2];   // [1024, 1024]
    const float* bproj = (const float*)d_in[3];   // [1024]
    float* out = (float*)d_out;

    float* qkv;
    __half *xh, *ah, *wqh, *wph;
    cudaGetSymbolAddress((void**)&qkv, g_qkv);
    cudaGetSymbolAddress((void**)&xh, g_xh);
    cudaGetSymbolAddress((void**)&ah, g_ah);
    cudaGetSymbolAddress((void**)&wqh, g_wqh);
    cudaGetSymbolAddress((void**)&wph, g_wph);

    const int spat_smem = 2 * 256 * 64 * (int)sizeof(float);   // 131072
    const int temp_smem = 2 * 16 * TKS * (int)sizeof(float);   // 66048
    cudaFuncSetAttribute(spatial_attn_kernel,
                         cudaFuncAttributeMaxDynamicSharedMemorySize, spat_smem);
    cudaFuncSetAttribute(temporal_attn_kernel,
                         cudaFuncAttributeMaxDynamicSharedMemorySize, temp_smem);
    cudaFuncSetAttribute(gemm_f16_mma,
                         cudaFuncAttributeMaxDynamicSharedMemorySize, GEMM_SMEM_DYN);

    // 0) fp16 conversions / weight transposes
    const int n4x = MTOK * DD / 4;
    convert_h<<<n4x / 256, 256>>>((const float4*)x, (uint2*)xh, n4x);
    transpose_h<<<dim3(QKVC / 32, DD / 32), dim3(32, 8)>>>(Wqkv, wqh, DD, QKVC);
    transpose_h<<<dim3(DD / 32, DD / 32), dim3(32, 8)>>>(Wproj, wph, DD, DD);

    // 1) qkv = x @ Wqkv   (HMMA fp16)
    gemm_f16_mma<<<dim3(QKVC / 128, MTOK / 128), 256, GEMM_SMEM_DYN>>>(
        xh, wqh, qkv, MTOK, QKVC, DD, nullptr);

    // 2) attention -> ah (fp16)
    spatial_attn_kernel<<<NB * TT * HEADS, 256, spat_smem>>>(qkv, ah);
    temporal_attn_kernel<<<NB * SS, 128, temp_smem>>>(qkv, ah);

    // 3) out = att @ Wproj + bproj   (HMMA fp16)
    gemm_f16_mma<<<dim3(DD / 128, MTOK / 128), 256, GEMM_SMEM_DYN>>>(
        ah, wph, out, MTOK, DD, DD, bproj);
}

// round 13
// speedup vs baseline: 6.0712x; 1.5321x over previous
#include <cuda_runtime.h>
#include <cuda_fp16.h>
#include <cstdint>
#include <math.h>

// Shapes (fixed by the problem)
#define NB   2
#define TT   16
#define SS   256
#define DD   1024
#define MTOK (NB*TT*SS)        // 8192 tokens
#define QKVC (3*DD)            // 3072
#define HEADS 8
#define DH    64
#define SCALE 0.125f           // (1024/16)^-0.5

// ---------------------------------------------------------------------------
// Scratch (static device allocations — no cudaMalloc anywhere)
// ---------------------------------------------------------------------------
__device__ __align__(16) __half g_qkvh[MTOK * QKVC];   // [8192, 3072] fp16
__device__ __align__(16) __half g_xh[MTOK * DD];       // x in fp16
__device__ __align__(16) __half g_ah[MTOK * DD];       // attention out fp16
__device__ __align__(16) __half g_wqh[QKVC * DD];      // Wqkv^T [3072,1024] fp16
__device__ __align__(16) __half g_wph[DD * DD];        // Wproj^T [1024,1024] fp16

// ---------------------------------------------------------------------------
// PTX helpers: mma.sync + ldmatrix + cp.async (sm_80+, safe on sm_103 target)
// ---------------------------------------------------------------------------
__device__ __forceinline__ uint32_t smem_to_u32(const void* p) {
    uint32_t a;
    asm("{ .reg .u64 t; cvta.to.shared.u64 t, %1; cvt.u32.u64 %0, t; }" : "=r"(a) : "l"(p));
    return a;
}

__device__ __forceinline__ void ldmatrix_x4(uint32_t& r0, uint32_t& r1,
                                            uint32_t& r2, uint32_t& r3, uint32_t addr) {
    asm volatile("ldmatrix.sync.aligned.m8n8.x4.shared.b16 {%0,%1,%2,%3}, [%4];"
                 : "=r"(r0), "=r"(r1), "=r"(r2), "=r"(r3) : "r"(addr));
}

__device__ __forceinline__ void ldmatrix_x4_trans(uint32_t& r0, uint32_t& r1,
                                                  uint32_t& r2, uint32_t& r3, uint32_t addr) {
    asm volatile("ldmatrix.sync.aligned.m8n8.x4.trans.shared.b16 {%0,%1,%2,%3}, [%4];"
                 : "=r"(r0), "=r"(r1), "=r"(r2), "=r"(r3) : "r"(addr));
}

__device__ __forceinline__ void mma16816(float* d, uint32_t a0, uint32_t a1,
                                         uint32_t a2, uint32_t a3,
                                         uint32_t b0, uint32_t b1) {
    asm volatile(
        "mma.sync.aligned.m16n8k16.row.col.f32.f16.f16.f32 "
        "{%0,%1,%2,%3}, {%4,%5,%6,%7}, {%8,%9}, {%0,%1,%2,%3};"
        : "+f"(d[0]), "+f"(d[1]), "+f"(d[2]), "+f"(d[3])
        : "r"(a0), "r"(a1), "r"(a2), "r"(a3), "r"(b0), "r"(b1));
}

__device__ __forceinline__ void cp_async16(uint32_t saddr, const void* gaddr) {
    asm volatile("cp.async.cg.shared.global [%0], [%1], 16;" :: "r"(saddr), "l"(gaddr));
}

__device__ __forceinline__ uint32_t f2h2(float lo, float hi) {
    __half2 h = __floats2half2_rn(lo, hi);
    return *(uint32_t*)&h;
}

// ---------------------------------------------------------------------------
// fp16 tensor-core GEMM: C[M,N] = A[M,K] @ B[N,K]^T (+ bias), fp32 accumulate.
// OutT = float (with optional bias) or __half.
// CTA tile 128x128, 8 warps (warp tile 32x64), K-chunk 32,
// 2-stage cp.async double buffering (2 tiles/stage, 40 KB dynamic smem).
// ---------------------------------------------------------------------------
#define RS 40            // padded row stride in fp16 elems (80 bytes)
#define TILE_F (128*RS)  // fp16 elems per tile region (5120)
#define GEMM_SMEM_DYN (2 * 2 * TILE_F * 2)   // 40960 bytes

template <typename OutT>
__global__ __launch_bounds__(256, 2) void gemm_f16_mma(
    const __half* __restrict__ A, const __half* __restrict__ B,
    OutT* __restrict__ C, int M, int N, int K,
    const float* __restrict__ bias)
{
    extern __shared__ __half dsm[];  // [2 stages][2 tiles][TILE_F]

    const int tid  = threadIdx.x;
    const int wid  = tid >> 5;
    const int lane = tid & 31;
    const int warp_m = wid & 3;
    const int warp_n = wid >> 2;
    const int m0 = blockIdx.y * 128;
    const int n0 = blockIdx.x * 128;

    const uint32_t sbase = smem_to_u32(dsm);
    #define TILE_U(s, t) (sbase + (uint32_t)(((s) * 2 + (t)) * TILE_F * 2))

    float acc[2][8][4];
    #pragma unroll
    for (int i = 0; i < 2; i++)
        #pragma unroll
        for (int j = 0; j < 8; j++)
            #pragma unroll
            for (int q = 0; q < 4; q++) acc[i][j][q] = 0.f;

    const int lr0 = tid >> 2;
    const int lc0 = tid & 3;
    const int niter = K / 32;

    {
        #pragma unroll
        for (int half = 0; half < 2; half++) {
            const int r = lr0 + half * 64;
            const uint32_t soff = (uint32_t)(r * RS + lc0 * 8) * 2;
            cp_async16(TILE_U(0, 0) + soff, A + (size_t)(m0 + r) * K + lc0 * 8);
            cp_async16(TILE_U(0, 1) + soff, B + (size_t)(n0 + r) * K + lc0 * 8);
        }
        asm volatile("cp.async.commit_group;");
    }

    for (int it = 0; it < niter; it++) {
        const int stage = it & 1;
        if (it + 1 < niter) {
            const int k0n = (it + 1) * 32;
            const int sn = stage ^ 1;
            #pragma unroll
            for (int half = 0; half < 2; half++) {
                const int r = lr0 + half * 64;
                const uint32_t soff = (uint32_t)(r * RS + lc0 * 8) * 2;
                cp_async16(TILE_U(sn, 0) + soff, A + (size_t)(m0 + r) * K + k0n + lc0 * 8);
                cp_async16(TILE_U(sn, 1) + soff, B + (size_t)(n0 + r) * K + k0n + lc0 * 8);
            }
            asm volatile("cp.async.commit_group;");
            asm volatile("cp.async.wait_group 1;");
        } else {
            asm volatile("cp.async.wait_group 0;");
        }
        __syncthreads();

        const uint32_t uA = TILE_U(stage, 0);
        const uint32_t uB = TILE_U(stage, 1);

        #pragma unroll
        for (int ks = 0; ks < 2; ks++) {
            uint32_t ah[2][4];
            const int am = (lane & 15);
            const int ak = (ks * 16 + ((lane >> 4) << 3)) * 2;
            #pragma unroll
            for (int ms = 0; ms < 2; ms++) {
                const uint32_t arow = (uint32_t)(warp_m * 32 + ms * 16 + am) * (RS * 2) + ak;
                ldmatrix_x4(ah[ms][0], ah[ms][1], ah[ms][2], ah[ms][3], uA + arow);
            }
            const int bn = (lane & 7) + ((lane >> 4) << 3);
            const int bk = (ks * 16 + (((lane >> 3) & 1) << 3)) * 2;
            uint32_t bh[4][4];
            #pragma unroll
            for (int nn = 0; nn < 4; nn++) {
                const uint32_t brow = (uint32_t)(warp_n * 64 + nn * 16 + bn) * (RS * 2) + bk;
                ldmatrix_x4(bh[nn][0], bh[nn][1], bh[nn][2], bh[nn][3], uB + brow);
            }
            #pragma unroll
            for (int ms = 0; ms < 2; ms++)
                #pragma unroll
                for (int nn = 0; nn < 4; nn++) {
                    mma16816(acc[ms][nn * 2 + 0], ah[ms][0], ah[ms][1], ah[ms][2], ah[ms][3],
                             bh[nn][0], bh[nn][1]);
                    mma16816(acc[ms][nn * 2 + 1], ah[ms][0], ah[ms][1], ah[ms][2], ah[ms][3],
                             bh[nn][2], bh[nn][3]);
                }
        }
        __syncthreads();
    }
    #undef TILE_U

    const int orow = m0 + warp_m * 32 + (lane >> 2);
    const int ocol0 = n0 + warp_n * 64 + (lane & 3) * 2;
    #pragma unroll
    for (int ms = 0; ms < 2; ms++) {
        #pragma unroll
        for (int nf = 0; nf < 8; nf++) {
            const int col = ocol0 + nf * 8;
            if constexpr (sizeof(OutT) == 2) {
                uint32_t u0 = f2h2(acc[ms][nf][0], acc[ms][nf][1]);
                uint32_t u1 = f2h2(acc[ms][nf][2], acc[ms][nf][3]);
                *(uint32_t*)((__half*)C + (size_t)(orow + ms * 16) * N + col) = u0;
                *(uint32_t*)((__half*)C + (size_t)(orow + ms * 16 + 8) * N + col) = u1;
            } else {
                float b0 = 0.f, b1 = 0.f;
                if (bias) { b0 = bias[col]; b1 = bias[col + 1]; }
                float2 v0 = make_float2(acc[ms][nf][0] + b0, acc[ms][nf][1] + b1);
                float2 v1 = make_float2(acc[ms][nf][2] + b0, acc[ms][nf][3] + b1);
                *(float2*)((float*)C + (size_t)(orow + ms * 16) * N + col) = v0;
                *(float2*)((float*)C + (size_t)(orow + ms * 16 + 8) * N + col) = v1;
            }
        }
    }
}

// ---------------------------------------------------------------------------
// fp32 -> fp16 convert / transpose
// ---------------------------------------------------------------------------
__global__ __launch_bounds__(256) void convert_h(
    const float4* __restrict__ in, uint2* __restrict__ outh, int n4)
{
    int i = blockIdx.x * blockDim.x + threadIdx.x;
    if (i >= n4) return;
    float4 v = in[i];
    union { __half b[4]; uint2 u; } H;
    H.b[0] = __float2half_rn(v.x);
    H.b[1] = __float2half_rn(v.y);
    H.b[2] = __float2half_rn(v.z);
    H.b[3] = __float2half_rn(v.w);
    outh[i] = H.u;
}

__global__ __launch_bounds__(256) void transpose_h(
    const float* __restrict__ W, __half* __restrict__ T, int K, int N)
{
    __shared__ float tile[32][33];
    const int n0 = blockIdx.x * 32;
    const int k0 = blockIdx.y * 32;
    for (int i = threadIdx.y; i < 32; i += 8)
        tile[i][threadIdx.x] = W[(size_t)(k0 + i) * N + n0 + threadIdx.x];
    __syncthreads();
    for (int i = threadIdx.y; i < 32; i += 8) {
        float v = tile[threadIdx.x][i];
        T[(size_t)(n0 + i) * K + k0 + threadIdx.x] = __float2half_rn(v);
    }
}

// ---------------------------------------------------------------------------
// Spatial attention via HMMA (flash-style): one block per (n,t,h).
// 8 warps x 32 queries; K/V chunks of 64 keys; online softmax.
// Q/K/V in smem fp16, rows padded to 144B (RS2=72 halves).
// ---------------------------------------------------------------------------
#define RS2 72
#define SPAT_SMEM (3 * 256 * RS2 * 2)   // 110592 bytes

__global__ __launch_bounds__(256, 1) void spatial_attn_mma(
    const __half* __restrict__ qkvh, __half* __restrict__ ah)
{
    extern __shared__ __half sm2[];
    __half* Qs = sm2;
    __half* Ks = sm2 + 256 * RS2;
    __half* Vs = sm2 + 2 * 256 * RS2;

    const int b = blockIdx.x;
    const int h = b & 7;
    const int t = (b >> 3) & 15;
    const int n = b >> 7;
    const int tid = threadIdx.x;
    const int wid = tid >> 5;
    const int lane = tid & 31;
    const int frame_base = (n * TT + t) * SS;

    // Fill Q/K/V smem (fp16, uint2 = 4 halves granularity; RS2/4 = 18)
    {
        const uint2* src = (const uint2*)qkvh;
        uint2* Q2 = (uint2*)Qs;
        uint2* K2 = (uint2*)Ks;
        uint2* V2 = (uint2*)Vs;
        for (int idx = tid; idx < 256 * 16; idx += 256) {
            const int s  = idx >> 4;
            const int d4 = idx & 15;
            const int base = (frame_base + s) * (QKVC / 4);
            const int dst = s * 18 + d4;
            Q2[dst] = src[base + h * 16 + d4];            // q_s cols [0,512)
            K2[dst] = src[base + 256 + h * 16 + d4];      // k_s cols [1024,1536)
            V2[dst] = src[base + 512 + h * 16 + d4];      // v_s cols [2048,2560)
        }
    }
    __syncthreads();

    const uint32_t uQ = smem_to_u32(Qs);
    const uint32_t uK = smem_to_u32(Ks);
    const uint32_t uV = smem_to_u32(Vs);

    // Hoist Q fragments (A-pattern): qf[ms][kd][4]
    uint32_t qf[2][4][4];
    {
        const int am = lane & 15;
        const int ac = (lane >> 4) << 4;   // byte offset of 8-half group
        #pragma unroll
        for (int ms = 0; ms < 2; ms++)
            #pragma unroll
            for (int kd = 0; kd < 4; kd++) {
                const uint32_t addr = uQ + (uint32_t)(wid * 32 + ms * 16 + am) * (RS2 * 2)
                                         + kd * 32 + ac;
                ldmatrix_x4(qf[ms][kd][0], qf[ms][kd][1], qf[ms][kd][2], qf[ms][kd][3], addr);
            }
    }

    float O[2][8][4];
    #pragma unroll
    for (int i = 0; i < 2; i++)
        #pragma unroll
        for (int j = 0; j < 8; j++)
            #pragma unroll
            for (int q = 0; q < 4; q++) O[i][j][q] = 0.f;
    float mrow[2][2] = { {-1e30f, -1e30f}, {-1e30f, -1e30f} };
    float lrow[2][2] = { {0.f, 0.f}, {0.f, 0.f} };

    const int bn = (lane & 7) + ((lane >> 4) << 3);        // B-pattern row
    const int bkh = ((lane >> 3) & 1) << 4;                // B-pattern byte half
    const int am = lane & 15;                              // A-pattern row
    const int ac = (lane >> 4) << 4;                       // A-pattern byte half

    for (int kc = 0; kc < 256; kc += 64) {
        // ---- S = Q @ K^T (chunk 32q x 64k) ----
        float S[2][8][4];
        #pragma unroll
        for (int i = 0; i < 2; i++)
            #pragma unroll
            for (int j = 0; j < 8; j++)
                #pragma unroll
                for (int q = 0; q < 4; q++) S[i][j][q] = 0.f;

        #pragma unroll
        for (int t16 = 0; t16 < 4; t16++) {
            uint32_t kf[4][4];
            #pragma unroll
            for (int kd = 0; kd < 4; kd++) {
                const uint32_t addr = uK + (uint32_t)(kc + t16 * 16 + bn) * (RS2 * 2)
                                         + kd * 32 + bkh;
                ldmatrix_x4(kf[kd][0], kf[kd][1], kf[kd][2], kf[kd][3], addr);
            }
            #pragma unroll
            for (int ms = 0; ms < 2; ms++)
                #pragma unroll
                for (int kd = 0; kd < 4; kd++) {
                    mma16816(S[ms][t16 * 2 + 0], qf[ms][kd][0], qf[ms][kd][1],
                             qf[ms][kd][2], qf[ms][kd][3], kf[kd][0], kf[kd][1]);
                    mma16816(S[ms][t16 * 2 + 1], qf[ms][kd][0], qf[ms][kd][1],
                             qf[ms][kd][2], qf[ms][kd][3], kf[kd][2], kf[kd][3]);
                }
        }

        // ---- online softmax (scale folded into exp arg) ----
        #pragma unroll
        for (int ms = 0; ms < 2; ms++) {
            float mx0 = -1e30f, mx1 = -1e30f;
            #pragma unroll
            for (int nf = 0; nf < 8; nf++) {
                mx0 = fmaxf(mx0, fmaxf(S[ms][nf][0], S[ms][nf][1]));
                mx1 = fmaxf(mx1, fmaxf(S[ms][nf][2], S[ms][nf][3]));
            }
            mx0 = fmaxf(mx0, __shfl_xor_sync(0xffffffffu, mx0, 1));
            mx0 = fmaxf(mx0, __shfl_xor_sync(0xffffffffu, mx0, 2));
            mx1 = fmaxf(mx1, __shfl_xor_sync(0xffffffffu, mx1, 1));
            mx1 = fmaxf(mx1, __shfl_xor_sync(0xffffffffu, mx1, 2));

            const float mn0 = fmaxf(mrow[ms][0], mx0);
            const float mn1 = fmaxf(mrow[ms][1], mx1);
            const float corr0 = __expf(SCALE * (mrow[ms][0] - mn0));
            const float corr1 = __expf(SCALE * (mrow[ms][1] - mn1));
            mrow[ms][0] = mn0;
            mrow[ms][1] = mn1;
            const float o0 = SCALE * mn0;
            const float o1 = SCALE * mn1;

            float s0 = 0.f, s1 = 0.f;
            #pragma unroll
            for (int nf = 0; nf < 8; nf++) {
                S[ms][nf][0] = __expf(fmaf(S[ms][nf][0], SCALE, -o0));
                S[ms][nf][1] = __expf(fmaf(S[ms][nf][1], SCALE, -o0));
                S[ms][nf][2] = __expf(fmaf(S[ms][nf][2], SCALE, -o1));
                S[ms][nf][3] = __expf(fmaf(S[ms][nf][3], SCALE, -o1));
                s0 += S[ms][nf][0] + S[ms][nf][1];
                s1 += S[ms][nf][2] + S[ms][nf][3];
            }
            s0 += __shfl_xor_sync(0xffffffffu, s0, 1);
            s0 += __shfl_xor_sync(0xffffffffu, s0, 2);
            s1 += __shfl_xor_sync(0xffffffffu, s1, 1);
            s1 += __shfl_xor_sync(0xffffffffu, s1, 2);
            lrow[ms][0] = lrow[ms][0] * corr0 + s0;
            lrow[ms][1] = lrow[ms][1] * corr1 + s1;

            #pragma unroll
            for (int nf = 0; nf < 8; nf++) {
                O[ms][nf][0] *= corr0; O[ms][nf][1] *= corr0;
                O[ms][nf][2] *= corr1; O[ms][nf][3] *= corr1;
            }
        }

        // ---- O += P @ V (keys = k-dim, trans ldmatrix on V) ----
        #pragma unroll
        for (int j = 0; j < 4; j++) {
            uint32_t vf[4][4];
            #pragma unroll
            for (int ng = 0; ng < 4; ng++) {
                const uint32_t addr = uV + (uint32_t)(kc + j * 16 + am) * (RS2 * 2)
                                         + ng * 32 + ac;
                ldmatrix_x4_trans(vf[ng][0], vf[ng][1], vf[ng][2], vf[ng][3], addr);
            }
            #pragma unroll
            for (int ms = 0; ms < 2; ms++) {
                const uint32_t a0 = f2h2(S[ms][2 * j][0],     S[ms][2 * j][1]);
                const uint32_t a1 = f2h2(S[ms][2 * j][2],     S[ms][2 * j][3]);
                const uint32_t a2 = f2h2(S[ms][2 * j + 1][0], S[ms][2 * j + 1][1]);
                const uint32_t a3 = f2h2(S[ms][2 * j + 1][2], S[ms][2 * j + 1][3]);
                #pragma unroll
                for (int ng = 0; ng < 4; ng++) {
                    mma16816(O[ms][ng * 2 + 0], a0, a1, a2, a3, vf[ng][0], vf[ng][1]);
                    mma16816(O[ms][ng * 2 + 1], a0, a1, a2, a3, vf[ng][2], vf[ng][3]);
                }
            }
        }
    }

    // ---- epilogue: normalize, write fp16 (cols [0,512) of att) ----
    #pragma unroll
    for (int ms = 0; ms < 2; ms++) {
        const float inv0 = 1.f / lrow[ms][0];
        const float inv1 = 1.f / lrow[ms][1];
        const int row0 = frame_base + wid * 32 + ms * 16 + (lane >> 2);
        const int col0 = h * 64 + (lane & 3) * 2;
        #pragma unroll
        for (int nf = 0; nf < 8; nf++) {
            const int col = col0 + nf * 8;
            uint32_t u0 = f2h2(O[ms][nf][0] * inv0, O[ms][nf][1] * inv0);
            uint32_t u1 = f2h2(O[ms][nf][2] * inv1, O[ms][nf][3] * inv1);
            *(uint32_t*)(ah + (size_t)row0 * DD + col) = u0;
            *(uint32_t*)(ah + (size_t)(row0 + 8) * DD + col) = u1;
        }
    }
}

// ---------------------------------------------------------------------------
// Temporal attention: reads fp16 qkv (converts at fill), writes fp16.
// ---------------------------------------------------------------------------
#define TKS 516

__device__ __forceinline__ float4 h4_to_f4(uint2 raw) {
    __half2* hp = (__half2*)&raw;
    float2 f0 = __half22float2(hp[0]);
    float2 f1 = __half22float2(hp[1]);
    return make_float4(f0.x, f0.y, f1.x, f1.y);
}

__global__ __launch_bounds__(128, 1) void temporal_attn_kernel(
    const __half* __restrict__ qkvh, __half* __restrict__ ah)
{
    extern __shared__ float fsm[];
    float* Ks = fsm;
    float* Vs = fsm + 16 * TKS;

    const int b = blockIdx.x;
    const int s = b & 255;
    const int n = b >> 8;
    const int tid = threadIdx.x;

    for (int idx = tid; idx < 16 * 128; idx += 128) {
        int t  = idx >> 7;
        int c4 = idx & 127;
        int tok = (n * TT + t) * SS + s;
        const uint2* base = (const uint2*)(qkvh + (size_t)tok * QKVC);
        ((float4*)(Ks + t * TKS))[c4] = h4_to_f4(base[384 + c4]);   // k_t cols [1536,2048)
        ((float4*)(Vs + t * TKS))[c4] = h4_to_f4(base[640 + c4]);   // v_t cols [2560,3072)
    }
    __syncthreads();

    const int h  = tid >> 4;
    const int tq = tid & 15;
    const int tokq = (n * TT + tq) * SS + s;

    float4 q[16];
    const uint2* qb = (const uint2*)(qkvh + (size_t)tokq * QKVC);
    #pragma unroll
    for (int i = 0; i < 16; i++) q[i] = h4_to_f4(qb[128 + h * 16 + i]);  // q_t cols [512,1024)

    float l[16];
    float m = -1e30f;
    #pragma unroll
    for (int kt = 0; kt < 16; kt++) {
        const float4* kp = (const float4*)(Ks + kt * TKS + h * 64);
        float dot = 0.f;
        #pragma unroll
        for (int i = 0; i < 16; i++) {
            float4 kv = kp[i];
            dot += q[i].x * kv.x + q[i].y * kv.y + q[i].z * kv.z + q[i].w * kv.w;
        }
        l[kt] = dot * SCALE;
        m = fmaxf(m, l[kt]);
    }
    float ssum = 0.f;
    #pragma unroll
    for (int kt = 0; kt < 16; kt++) { l[kt] = __expf(l[kt] - m); ssum += l[kt]; }
    float inv = 1.f / ssum;

    float4 acc[16];
    #pragma unroll
    for (int i = 0; i < 16; i++) acc[i] = make_float4(0.f, 0.f, 0.f, 0.f);
    #pragma unroll
    for (int kt = 0; kt < 16; kt++) {
        float p = l[kt] * inv;
        const float4* vp = (const float4*)(Vs + kt * TKS + h * 64);
        #pragma unroll
        for (int i = 0; i < 16; i++) {
            float4 vv = vp[i];
            acc[i].x += p * vv.x; acc[i].y += p * vv.y;
            acc[i].z += p * vv.z; acc[i].w += p * vv.w;
        }
    }

    uint2* out4 = (uint2*)ah;
    #pragma unroll
    for (int i = 0; i < 16; i++) {
        union { __half b[4]; uint2 u; } H;
        H.b[0] = __float2half_rn(acc[i].x);
        H.b[1] = __float2half_rn(acc[i].y);
        H.b[2] = __float2half_rn(acc[i].z);
        H.b[3] = __float2half_rn(acc[i].w);
        out4[tokq * (DD / 4) + 128 + h * 16 + i] = H.u;  // cols [512,1024)
    }
}

// ---------------------------------------------------------------------------
// Launch
// ---------------------------------------------------------------------------
extern "C" void kernel_launch(void* const* d_in, const int* in_sizes, int n_in,
                              void* d_out, int out_size)
{
    const float* x     = (const float*)d_in[0];
    const float* Wqkv  = (const float*)d_in[1];
    const float* Wproj = (const float*)d_in[2];
    const float* bproj = (const float*)d_in[3];
    float* out = (float*)d_out;

    __half *qkvh, *xh, *ah, *wqh, *wph;
    cudaGetSymbolAddress((void**)&qkvh, g_qkvh);
    cudaGetSymbolAddress((void**)&xh, g_xh);
    cudaGetSymbolAddress((void**)&ah, g_ah);
    cudaGetSymbolAddress((void**)&wqh, g_wqh);
    cudaGetSymbolAddress((void**)&wph, g_wph);

    const int temp_smem = 2 * 16 * TKS * (int)sizeof(float);   // 66048
    cudaFuncSetAttribute(spatial_attn_mma,
                         cudaFuncAttributeMaxDynamicSharedMemorySize, SPAT_SMEM);
    cudaFuncSetAttribute(temporal_attn_kernel,
                         cudaFuncAttributeMaxDynamicSharedMemorySize, temp_smem);
    cudaFuncSetAttribute(gemm_f16_mma<__half>,
                         cudaFuncAttributeMaxDynamicSharedMemorySize, GEMM_SMEM_DYN);
    cudaFuncSetAttribute(gemm_f16_mma<float>,
                         cudaFuncAttributeMaxDynamicSharedMemorySize, GEMM_SMEM_DYN);

    // 0) fp16 conversions / weight transposes
    const int n4x = MTOK * DD / 4;
    convert_h<<<n4x / 256, 256>>>((const float4*)x, (uint2*)xh, n4x);
    transpose_h<<<dim3(QKVC / 32, DD / 32), dim3(32, 8)>>>(Wqkv, wqh, DD, QKVC);
    transpose_h<<<dim3(DD / 32, DD / 32), dim3(32, 8)>>>(Wproj, wph, DD, DD);

    // 1) qkv = x @ Wqkv  (HMMA, fp16 output)
    gemm_f16_mma<__half><<<dim3(QKVC / 128, MTOK / 128), 256, GEMM_SMEM_DYN>>>(
        xh, wqh, qkvh, MTOK, QKVC, DD, nullptr);

    // 2) attention -> ah (fp16)
    spatial_attn_mma<<<NB * TT * HEADS, 256, SPAT_SMEM>>>(qkvh, ah);
    temporal_attn_kernel<<<NB * SS, 128, temp_smem>>>(qkvh, ah);

    // 3) out = att @ Wproj + bproj  (HMMA, fp32 output)
    gemm_f16_mma<float><<<dim3(DD / 128, MTOK / 128), 256, GEMM_SMEM_DYN>>>(
        ah, wph, out, MTOK, DD, DD, bproj);
}

// round 14
// speedup vs baseline: 6.5543x; 1.0796x over previous
#include <cuda_runtime.h>
#include <cuda_fp16.h>
#include <cstdint>
#include <math.h>

// Shapes (fixed by the problem)
#define NB   2
#define TT   16
#define SS   256
#define DD   1024
#define MTOK (NB*TT*SS)        // 8192 tokens
#define QKVC (3*DD)            // 3072
#define HEADS 8
#define DH    64
#define SCALE 0.125f           // (1024/16)^-0.5

// ---------------------------------------------------------------------------
// Scratch (static device allocations — no cudaMalloc anywhere)
// ---------------------------------------------------------------------------
__device__ __align__(16) __half g_qkvh[MTOK * QKVC];   // [8192, 3072] fp16
__device__ __align__(16) __half g_xh[MTOK * DD];       // x in fp16
__device__ __align__(16) __half g_ah[MTOK * DD];       // attention out fp16
__device__ __align__(16) __half g_wqh[QKVC * DD];      // Wqkv^T [3072,1024] fp16
__device__ __align__(16) __half g_wph[DD * DD];        // Wproj^T [1024,1024] fp16

// ---------------------------------------------------------------------------
// PTX helpers
// ---------------------------------------------------------------------------
__device__ __forceinline__ uint32_t smem_to_u32(const void* p) {
    uint32_t a;
    asm("{ .reg .u64 t; cvta.to.shared.u64 t, %1; cvt.u32.u64 %0, t; }" : "=r"(a) : "l"(p));
    return a;
}

__device__ __forceinline__ void ldmatrix_x4(uint32_t& r0, uint32_t& r1,
                                            uint32_t& r2, uint32_t& r3, uint32_t addr) {
    asm volatile("ldmatrix.sync.aligned.m8n8.x4.shared.b16 {%0,%1,%2,%3}, [%4];"
                 : "=r"(r0), "=r"(r1), "=r"(r2), "=r"(r3) : "r"(addr));
}

__device__ __forceinline__ void ldmatrix_x4_trans(uint32_t& r0, uint32_t& r1,
                                                  uint32_t& r2, uint32_t& r3, uint32_t addr) {
    asm volatile("ldmatrix.sync.aligned.m8n8.x4.trans.shared.b16 {%0,%1,%2,%3}, [%4];"
                 : "=r"(r0), "=r"(r1), "=r"(r2), "=r"(r3) : "r"(addr));
}

__device__ __forceinline__ void mma16816(float* d, uint32_t a0, uint32_t a1,
                                         uint32_t a2, uint32_t a3,
                                         uint32_t b0, uint32_t b1) {
    asm volatile(
        "mma.sync.aligned.m16n8k16.row.col.f32.f16.f16.f32 "
        "{%0,%1,%2,%3}, {%4,%5,%6,%7}, {%8,%9}, {%0,%1,%2,%3};"
        : "+f"(d[0]), "+f"(d[1]), "+f"(d[2]), "+f"(d[3])
        : "r"(a0), "r"(a1), "r"(a2), "r"(a3), "r"(b0), "r"(b1));
}

__device__ __forceinline__ void cp_async16(uint32_t saddr, const void* gaddr) {
    asm volatile("cp.async.cg.shared.global [%0], [%1], 16;" :: "r"(saddr), "l"(gaddr));
}

__device__ __forceinline__ uint32_t f2h2(float lo, float hi) {
    __half2 h = __floats2half2_rn(lo, hi);
    return *(uint32_t*)&h;
}

// ---------------------------------------------------------------------------
// fp16 tensor-core GEMM: C[M,N] = A[M,K] @ B[N,K]^T (+ bias), fp32 accumulate.
// CTA tile 128x128, 4 warps (warp tile 64x64), K-chunk 32,
// 3-stage cp.async pipeline (2 tiles/stage, 60 KB dynamic smem), 2 CTAs/SM.
// Warp tile 64x64: 8 ldmatrix.x4 per 32 MMAs -> smem crossbar no longer co-limits.
// ---------------------------------------------------------------------------
#define RS 40            // padded row stride in fp16 elems (80 bytes)
#define TILE_F (128*RS)  // fp16 elems per tile region (5120)
#define NSTAGE 3
#define GEMM_SMEM_DYN (NSTAGE * 2 * TILE_F * 2)   // 61440 bytes

template <typename OutT>
__global__ __launch_bounds__(128, 2) void gemm_f16_mma(
    const __half* __restrict__ A, const __half* __restrict__ B,
    OutT* __restrict__ C, int M, int N, int K,
    const float* __restrict__ bias)
{
    extern __shared__ __half dsm[];  // [NSTAGE][2 tiles][TILE_F]

    const int tid  = threadIdx.x;
    const int wid  = tid >> 5;
    const int lane = tid & 31;
    const int warp_m = wid & 1;      // 0..1 -> 64 rows each
    const int warp_n = wid >> 1;     // 0..1 -> 64 cols each
    const int m0 = blockIdx.y * 128;
    const int n0 = blockIdx.x * 128;

    const uint32_t sbase = smem_to_u32(dsm);
    #define TILE_U(s, t) (sbase + (uint32_t)(((s) * 2 + (t)) * TILE_F * 2))

    float acc[4][8][4];
    #pragma unroll
    for (int i = 0; i < 4; i++)
        #pragma unroll
        for (int j = 0; j < 8; j++)
            #pragma unroll
            for (int q = 0; q < 4; q++) acc[i][j][q] = 0.f;

    const int niter = K / 32;

    // prefetch lambda: per tile 512 uint4; thread covers elem = tid + i*128
    auto prefetch = [&](int chunk, int stage) {
        const int k0 = chunk * 32;
        #pragma unroll
        for (int i = 0; i < 4; i++) {
            const int elem = tid + i * 128;
            const int r    = elem >> 2;
            const int c16  = elem & 3;
            const uint32_t soff = (uint32_t)(r * RS + c16 * 8) * 2;
            cp_async16(TILE_U(stage, 0) + soff, A + (size_t)(m0 + r) * K + k0 + c16 * 8);
            cp_async16(TILE_U(stage, 1) + soff, B + (size_t)(n0 + r) * K + k0 + c16 * 8);
        }
        asm volatile("cp.async.commit_group;");
    };

    prefetch(0, 0);
    prefetch(1, 1);

    const int am  = lane & 15;                        // A-pattern row
    const int akg = ((lane >> 4) << 3) * 2;           // A-pattern byte group
    const int bn  = (lane & 7) + ((lane >> 4) << 3);  // B-pattern row
    const int bkg = (((lane >> 3) & 1) << 3) * 2;     // B-pattern byte group

    int stage = 0, pstage = 2;
    for (int it = 0; it < niter; it++) {
        if (it + 1 < niter) {
            asm volatile("cp.async.wait_group 1;");
        } else {
            asm volatile("cp.async.wait_group 0;");
        }
        __syncthreads();

        if (it + 2 < niter) {
            prefetch(it + 2, pstage);
            pstage = (pstage == NSTAGE - 1) ? 0 : pstage + 1;
        }

        const uint32_t uA = TILE_U(stage, 0);
        const uint32_t uB = TILE_U(stage, 1);

        #pragma unroll
        for (int ks = 0; ks < 2; ks++) {
            uint32_t af[4][4];
            #pragma unroll
            for (int ms = 0; ms < 4; ms++) {
                const uint32_t arow = (uint32_t)(warp_m * 64 + ms * 16 + am) * (RS * 2)
                                      + ks * 32 + akg;
                ldmatrix_x4(af[ms][0], af[ms][1], af[ms][2], af[ms][3], uA + arow);
            }
            uint32_t bf[4][4];
            #pragma unroll
            for (int nn = 0; nn < 4; nn++) {
                const uint32_t brow = (uint32_t)(warp_n * 64 + nn * 16 + bn) * (RS * 2)
                                      + ks * 32 + bkg;
                ldmatrix_x4(bf[nn][0], bf[nn][1], bf[nn][2], bf[nn][3], uB + brow);
            }
            #pragma unroll
            for (int ms = 0; ms < 4; ms++)
                #pragma unroll
                for (int nn = 0; nn < 4; nn++) {
                    mma16816(acc[ms][nn * 2 + 0], af[ms][0], af[ms][1], af[ms][2], af[ms][3],
                             bf[nn][0], bf[nn][1]);
                    mma16816(acc[ms][nn * 2 + 1], af[ms][0], af[ms][1], af[ms][2], af[ms][3],
                             bf[nn][2], bf[nn][3]);
                }
        }
        stage = (stage == NSTAGE - 1) ? 0 : stage + 1;
    }
    #undef TILE_U

    // ---- epilogue ----
    #pragma unroll
    for (int ms = 0; ms < 4; ms++) {
        const int orow = m0 + warp_m * 64 + ms * 16 + (lane >> 2);
        const int ocol0 = n0 + warp_n * 64 + (lane & 3) * 2;
        #pragma unroll
        for (int nf = 0; nf < 8; nf++) {
            const int col = ocol0 + nf * 8;
            if constexpr (sizeof(OutT) == 2) {
                uint32_t u0 = f2h2(acc[ms][nf][0], acc[ms][nf][1]);
                uint32_t u1 = f2h2(acc[ms][nf][2], acc[ms][nf][3]);
                *(uint32_t*)((__half*)C + (size_t)orow * N + col) = u0;
                *(uint32_t*)((__half*)C + (size_t)(orow + 8) * N + col) = u1;
            } else {
                float b0 = 0.f, b1 = 0.f;
                if (bias) { b0 = bias[col]; b1 = bias[col + 1]; }
                float2 v0 = make_float2(acc[ms][nf][0] + b0, acc[ms][nf][1] + b1);
                float2 v1 = make_float2(acc[ms][nf][2] + b0, acc[ms][nf][3] + b1);
                *(float2*)((float*)C + (size_t)orow * N + col) = v0;
                *(float2*)((float*)C + (size_t)(orow + 8) * N + col) = v1;
            }
        }
    }
}

// ---------------------------------------------------------------------------
// fp32 -> fp16 convert / transpose
// ---------------------------------------------------------------------------
__global__ __launch_bounds__(256) void convert_h(
    const float4* __restrict__ in, uint2* __restrict__ outh, int n4)
{
    int i = blockIdx.x * blockDim.x + threadIdx.x;
    if (i >= n4) return;
    float4 v = in[i];
    union { __half b[4]; uint2 u; } H;
    H.b[0] = __float2half_rn(v.x);
    H.b[1] = __float2half_rn(v.y);
    H.b[2] = __float2half_rn(v.z);
    H.b[3] = __float2half_rn(v.w);
    outh[i] = H.u;
}

__global__ __launch_bounds__(256) void transpose_h(
    const float* __restrict__ W, __half* __restrict__ T, int K, int N)
{
    __shared__ float tile[32][33];
    const int n0 = blockIdx.x * 32;
    const int k0 = blockIdx.y * 32;
    for (int i = threadIdx.y; i < 32; i += 8)
        tile[i][threadIdx.x] = W[(size_t)(k0 + i) * N + n0 + threadIdx.x];
    __syncthreads();
    for (int i = threadIdx.y; i < 32; i += 8) {
        float v = tile[threadIdx.x][i];
        T[(size_t)(n0 + i) * K + k0 + threadIdx.x] = __float2half_rn(v);
    }
}

// ---------------------------------------------------------------------------
// Spatial attention via HMMA (flash-style): one block per (n,t,h).
// ---------------------------------------------------------------------------
#define RS2 72
#define SPAT_SMEM (3 * 256 * RS2 * 2)   // 110592 bytes

__global__ __launch_bounds__(256, 1) void spatial_attn_mma(
    const __half* __restrict__ qkvh, __half* __restrict__ ah)
{
    extern __shared__ __half sm2[];
    __half* Qs = sm2;
    __half* Ks = sm2 + 256 * RS2;
    __half* Vs = sm2 + 2 * 256 * RS2;

    const int b = blockIdx.x;
    const int h = b & 7;
    const int t = (b >> 3) & 15;
    const int n = b >> 7;
    const int tid = threadIdx.x;
    const int wid = tid >> 5;
    const int lane = tid & 31;
    const int frame_base = (n * TT + t) * SS;

    {
        const uint2* src = (const uint2*)qkvh;
        uint2* Q2 = (uint2*)Qs;
        uint2* K2 = (uint2*)Ks;
        uint2* V2 = (uint2*)Vs;
        for (int idx = tid; idx < 256 * 16; idx += 256) {
            const int s  = idx >> 4;
            const int d4 = idx & 15;
            const int base = (frame_base + s) * (QKVC / 4);
            const int dst = s * 18 + d4;
            Q2[dst] = src[base + h * 16 + d4];
            K2[dst] = src[base + 256 + h * 16 + d4];
            V2[dst] = src[base + 512 + h * 16 + d4];
        }
    }
    __syncthreads();

    const uint32_t uQ = smem_to_u32(Qs);
    const uint32_t uK = smem_to_u32(Ks);
    const uint32_t uV = smem_to_u32(Vs);

    uint32_t qf[2][4][4];
    {
        const int am = lane & 15;
        const int ac = (lane >> 4) << 4;
        #pragma unroll
        for (int ms = 0; ms < 2; ms++)
            #pragma unroll
            for (int kd = 0; kd < 4; kd++) {
                const uint32_t addr = uQ + (uint32_t)(wid * 32 + ms * 16 + am) * (RS2 * 2)
                                         + kd * 32 + ac;
                ldmatrix_x4(qf[ms][kd][0], qf[ms][kd][1], qf[ms][kd][2], qf[ms][kd][3], addr);
            }
    }

    float O[2][8][4];
    #pragma unroll
    for (int i = 0; i < 2; i++)
        #pragma unroll
        for (int j = 0; j < 8; j++)
            #pragma unroll
            for (int q = 0; q < 4; q++) O[i][j][q] = 0.f;
    float mrow[2][2] = { {-1e30f, -1e30f}, {-1e30f, -1e30f} };
    float lrow[2][2] = { {0.f, 0.f}, {0.f, 0.f} };

    const int bn = (lane & 7) + ((lane >> 4) << 3);
    const int bkh = ((lane >> 3) & 1) << 4;
    const int am = lane & 15;
    const int ac = (lane >> 4) << 4;

    for (int kc = 0; kc < 256; kc += 64) {
        float S[2][8][4];
        #pragma unroll
        for (int i = 0; i < 2; i++)
            #pragma unroll
            for (int j = 0; j < 8; j++)
                #pragma unroll
                for (int q = 0; q < 4; q++) S[i][j][q] = 0.f;

        #pragma unroll
        for (int t16 = 0; t16 < 4; t16++) {
            uint32_t kf[4][4];
            #pragma unroll
            for (int kd = 0; kd < 4; kd++) {
                const uint32_t addr = uK + (uint32_t)(kc + t16 * 16 + bn) * (RS2 * 2)
                                         + kd * 32 + bkh;
                ldmatrix_x4(kf[kd][0], kf[kd][1], kf[kd][2], kf[kd][3], addr);
            }
            #pragma unroll
            for (int ms = 0; ms < 2; ms++)
                #pragma unroll
                for (int kd = 0; kd < 4; kd++) {
                    mma16816(S[ms][t16 * 2 + 0], qf[ms][kd][0], qf[ms][kd][1],
                             qf[ms][kd][2], qf[ms][kd][3], kf[kd][0], kf[kd][1]);
                    mma16816(S[ms][t16 * 2 + 1], qf[ms][kd][0], qf[ms][kd][1],
                             qf[ms][kd][2], qf[ms][kd][3], kf[kd][2], kf[kd][3]);
                }
        }

        #pragma unroll
        for (int ms = 0; ms < 2; ms++) {
            float mx0 = -1e30f, mx1 = -1e30f;
            #pragma unroll
            for (int nf = 0; nf < 8; nf++) {
                mx0 = fmaxf(mx0, fmaxf(S[ms][nf][0], S[ms][nf][1]));
                mx1 = fmaxf(mx1, fmaxf(S[ms][nf][2], S[ms][nf][3]));
            }
            mx0 = fmaxf(mx0, __shfl_xor_sync(0xffffffffu, mx0, 1));
            mx0 = fmaxf(mx0, __shfl_xor_sync(0xffffffffu, mx0, 2));
            mx1 = fmaxf(mx1, __shfl_xor_sync(0xffffffffu, mx1, 1));
            mx1 = fmaxf(mx1, __shfl_xor_sync(0xffffffffu, mx1, 2));

            const float mn0 = fmaxf(mrow[ms][0], mx0);
            const float mn1 = fmaxf(mrow[ms][1], mx1);
            const float corr0 = __expf(SCALE * (mrow[ms][0] - mn0));
            const float corr1 = __expf(SCALE * (mrow[ms][1] - mn1));
            mrow[ms][0] = mn0;
            mrow[ms][1] = mn1;
            const float o0 = SCALE * mn0;
            const float o1 = SCALE * mn1;

            float s0 = 0.f, s1 = 0.f;
            #pragma unroll
            for (int nf = 0; nf < 8; nf++) {
                S[ms][nf][0] = __expf(fmaf(S[ms][nf][0], SCALE, -o0));
                S[ms][nf][1] = __expf(fmaf(S[ms][nf][1], SCALE, -o0));
                S[ms][nf][2] = __expf(fmaf(S[ms][nf][2], SCALE, -o1));
                S[ms][nf][3] = __expf(fmaf(S[ms][nf][3], SCALE, -o1));
                s0 += S[ms][nf][0] + S[ms][nf][1];
                s1 += S[ms][nf][2] + S[ms][nf][3];
            }
            s0 += __shfl_xor_sync(0xffffffffu, s0, 1);
            s0 += __shfl_xor_sync(0xffffffffu, s0, 2);
            s1 += __shfl_xor_sync(0xffffffffu, s1, 1);
            s1 += __shfl_xor_sync(0xffffffffu, s1, 2);
            lrow[ms][0] = lrow[ms][0] * corr0 + s0;
            lrow[ms][1] = lrow[ms][1] * corr1 + s1;

            #pragma unroll
            for (int nf = 0; nf < 8; nf++) {
                O[ms][nf][0] *= corr0; O[ms][nf][1] *= corr0;
                O[ms][nf][2] *= corr1; O[ms][nf][3] *= corr1;
            }
        }

        #pragma unroll
        for (int j = 0; j < 4; j++) {
            uint32_t vf[4][4];
            #pragma unroll
            for (int ng = 0; ng < 4; ng++) {
                const uint32_t addr = uV + (uint32_t)(kc + j * 16 + am) * (RS2 * 2)
                                         + ng * 32 + ac;
                ldmatrix_x4_trans(vf[ng][0], vf[ng][1], vf[ng][2], vf[ng][3], addr);
            }
            #pragma unroll
            for (int ms = 0; ms < 2; ms++) {
                const uint32_t a0 = f2h2(S[ms][2 * j][0],     S[ms][2 * j][1]);
                const uint32_t a1 = f2h2(S[ms][2 * j][2],     S[ms][2 * j][3]);
                const uint32_t a2 = f2h2(S[ms][2 * j + 1][0], S[ms][2 * j + 1][1]);
                const uint32_t a3 = f2h2(S[ms][2 * j + 1][2], S[ms][2 * j + 1][3]);
                #pragma unroll
                for (int ng = 0; ng < 4; ng++) {
                    mma16816(O[ms][ng * 2 + 0], a0, a1, a2, a3, vf[ng][0], vf[ng][1]);
                    mma16816(O[ms][ng * 2 + 1], a0, a1, a2, a3, vf[ng][2], vf[ng][3]);
                }
            }
        }
    }

    #pragma unroll
    for (int ms = 0; ms < 2; ms++) {
        const float inv0 = 1.f / lrow[ms][0];
        const float inv1 = 1.f / lrow[ms][1];
        const int row0 = frame_base + wid * 32 + ms * 16 + (lane >> 2);
        const int col0 = h * 64 + (lane & 3) * 2;
        #pragma unroll
        for (int nf = 0; nf < 8; nf++) {
            const int col = col0 + nf * 8;
            uint32_t u0 = f2h2(O[ms][nf][0] * inv0, O[ms][nf][1] * inv0);
            uint32_t u1 = f2h2(O[ms][nf][2] * inv1, O[ms][nf][3] * inv1);
            *(uint32_t*)(ah + (size_t)row0 * DD + col) = u0;
            *(uint32_t*)(ah + (size_t)(row0 + 8) * DD + col) = u1;
        }
    }
}

// ---------------------------------------------------------------------------
// Temporal attention: reads fp16 qkv (converts at fill), writes fp16.
// ---------------------------------------------------------------------------
#define TKS 516

__device__ __forceinline__ float4 h4_to_f4(uint2 raw) {
    __half2* hp = (__half2*)&raw;
    float2 f0 = __half22float2(hp[0]);
    float2 f1 = __half22float2(hp[1]);
    return make_float4(f0.x, f0.y, f1.x, f1.y);
}

__global__ __launch_bounds__(128, 1) void temporal_attn_kernel(
    const __half* __restrict__ qkvh, __half* __restrict__ ah)
{
    extern __shared__ float fsm[];
    float* Ks = fsm;
    float* Vs = fsm + 16 * TKS;

    const int b = blockIdx.x;
    const int s = b & 255;
    const int n = b >> 8;
    const int tid = threadIdx.x;

    for (int idx = tid; idx < 16 * 128; idx += 128) {
        int t  = idx >> 7;
        int c4 = idx & 127;
        int tok = (n * TT + t) * SS + s;
        const uint2* base = (const uint2*)(qkvh + (size_t)tok * QKVC);
        ((float4*)(Ks + t * TKS))[c4] = h4_to_f4(base[384 + c4]);
        ((float4*)(Vs + t * TKS))[c4] = h4_to_f4(base[640 + c4]);
    }
    __syncthreads();

    const int h  = tid >> 4;
    const int tq = tid & 15;
    const int tokq = (n * TT + tq) * SS + s;

    float4 q[16];
    const uint2* qb = (const uint2*)(qkvh + (size_t)tokq * QKVC);
    #pragma unroll
    for (int i = 0; i < 16; i++) q[i] = h4_to_f4(qb[128 + h * 16 + i]);

    float l[16];
    float m = -1e30f;
    #pragma unroll
    for (int kt = 0; kt < 16; kt++) {
        const float4* kp = (const float4*)(Ks + kt * TKS + h * 64);
        float dot = 0.f;
        #pragma unroll
        for (int i = 0; i < 16; i++) {
            float4 kv = kp[i];
            dot += q[i].x * kv.x + q[i].y * kv.y + q[i].z * kv.z + q[i].w * kv.w;
        }
        l[kt] = dot * SCALE;
        m = fmaxf(m, l[kt]);
    }
    float ssum = 0.f;
    #pragma unroll
    for (int kt = 0; kt < 16; kt++) { l[kt] = __expf(l[kt] - m); ssum += l[kt]; }
    float inv = 1.f / ssum;

    float4 acc[16];
    #pragma unroll
    for (int i = 0; i < 16; i++) acc[i] = make_float4(0.f, 0.f, 0.f, 0.f);
    #pragma unroll
    for (int kt = 0; kt < 16; kt++) {
        float p = l[kt] * inv;
        const float4* vp = (const float4*)(Vs + kt * TKS + h * 64);
        #pragma unroll
        for (int i = 0; i < 16; i++) {
            float4 vv = vp[i];
            acc[i].x += p * vv.x; acc[i].y += p * vv.y;
            acc[i].z += p * vv.z; acc[i].w += p * vv.w;
        }
    }

    uint2* out4 = (uint2*)ah;
    #pragma unroll
    for (int i = 0; i < 16; i++) {
        union { __half b[4]; uint2 u; } H;
        H.b[0] = __float2half_rn(acc[i].x);
        H.b[1] = __float2half_rn(acc[i].y);
        H.b[2] = __float2half_rn(acc[i].z);
        H.b[3] = __float2half_rn(acc[i].w);
        out4[tokq * (DD / 4) + 128 + h * 16 + i] = H.u;
    }
}

// ---------------------------------------------------------------------------
// Launch
// ---------------------------------------------------------------------------
extern "C" void kernel_launch(void* const* d_in, const int* in_sizes, int n_in,
                              void* d_out, int out_size)
{
    const float* x     = (const float*)d_in[0];
    const float* Wqkv  = (const float*)d_in[1];
    const float* Wproj = (const float*)d_in[2];
    const float* bproj = (const float*)d_in[3];
    float* out = (float*)d_out;

    __half *qkvh, *xh, *ah, *wqh, *wph;
    cudaGetSymbolAddress((void**)&qkvh, g_qkvh);
    cudaGetSymbolAddress((void**)&xh, g_xh);
    cudaGetSymbolAddress((void**)&ah, g_ah);
    cudaGetSymbolAddress((void**)&wqh, g_wqh);
    cudaGetSymbolAddress((void**)&wph, g_wph);

    const int temp_smem = 2 * 16 * TKS * (int)sizeof(float);   // 66048
    cudaFuncSetAttribute(spatial_attn_mma,
                         cudaFuncAttributeMaxDynamicSharedMemorySize, SPAT_SMEM);
    cudaFuncSetAttribute(temporal_attn_kernel,
                         cudaFuncAttributeMaxDynamicSharedMemorySize, temp_smem);
    cudaFuncSetAttribute(gemm_f16_mma<__half>,
                         cudaFuncAttributeMaxDynamicSharedMemorySize, GEMM_SMEM_DYN);
    cudaFuncSetAttribute(gemm_f16_mma<float>,
                         cudaFuncAttributeMaxDynamicSharedMemorySize, GEMM_SMEM_DYN);

    // 0) fp16 conversions / weight transposes
    const int n4x = MTOK * DD / 4;
    convert_h<<<n4x / 256, 256>>>((const float4*)x, (uint2*)xh, n4x);
    transpose_h<<<dim3(QKVC / 32, DD / 32), dim3(32, 8)>>>(Wqkv, wqh, DD, QKVC);
    transpose_h<<<dim3(DD / 32, DD / 32), dim3(32, 8)>>>(Wproj, wph, DD, DD);

    // 1) qkv = x @ Wqkv  (HMMA, fp16 output)
    gemm_f16_mma<__half><<<dim3(QKVC / 128, MTOK / 128), 128, GEMM_SMEM_DYN>>>(
        xh, wqh, qkvh, MTOK, QKVC, DD, nullptr);

    // 2) attention -> ah (fp16)
    spatial_attn_mma<<<NB * TT * HEADS, 256, SPAT_SMEM>>>(qkvh, ah);
    temporal_attn_kernel<<<NB * SS, 128, temp_smem>>>(qkvh, ah);

    // 3) out = att @ Wproj + bproj  (HMMA, fp32 output)
    gemm_f16_mma<float><<<dim3(DD / 128, MTOK / 128), 128, GEMM_SMEM_DYN>>>(
        ah, wph, out, MTOK, DD, DD, bproj);
}